// round 15
// baseline (speedup 1.0000x reference)
#include <cuda_runtime.h>

typedef unsigned long long ull;

// ---------------- scratch (device globals; no allocation allowed) ----------------
static __device__ __align__(16) float g_a1[64*32*128*128];          // enc1 out
static __device__ __align__(16) float g_a2[64*64*64*64];            // enc2 out
static __device__ __align__(16) float g_q [64*16*64*64];            // quantized (decoder input)
static __device__ __align__(16) float g_d1[64*64*128*128];          // dec1 out
static __device__ __align__(16) float g_d2[64*32*256*256];          // dec2 out
static __device__ float g_pvq [1024];                               // per-block VQ sq-sum
static __device__ float g_pmse[2048];                               // per-block recon sq-sum

#define FULLMASK 0xffffffffu

// ---------------- f32x2 helpers ----------------
__device__ __forceinline__ ull pk2(float lo, float hi) {
    ull r;
    asm("mov.b64 %0, {%1, %2};" : "=l"(r)
        : "r"(__float_as_uint(lo)), "r"(__float_as_uint(hi)));
    return r;
}
__device__ __forceinline__ float2 upk2(ull p) {
    unsigned int a, b;
    asm("mov.b64 {%0, %1}, %2;" : "=r"(a), "=r"(b) : "l"(p));
    return make_float2(__uint_as_float(a), __uint_as_float(b));
}
__device__ __forceinline__ ull ffma2(ull a, ull b, ull c) {
    ull d;
    asm("fma.rn.f32x2 %0, %1, %2, %3;" : "=l"(d) : "l"(a), "l"(b), "l"(c));
    return d;
}
__device__ __forceinline__ float4 z4() { return make_float4(0.f, 0.f, 0.f, 0.f); }
__device__ __forceinline__ float rl(float v) { return fmaxf(v, 0.f); }

// ---------------- cp.async helpers ----------------
__device__ __forceinline__ void cpa16(void* smem_dst, const void* gsrc) {
    unsigned sa = (unsigned)__cvta_generic_to_shared(smem_dst);
    asm volatile("cp.async.ca.shared.global [%0], [%1], 16;" :: "r"(sa), "l"(gsrc));
}
#define CP_COMMIT() asm volatile("cp.async.commit_group;" ::: "memory")
#define CP_WAIT1()  asm volatile("cp.async.wait_group 1;" ::: "memory")
#define CP_WAIT0()  asm volatile("cp.async.wait_group 0;" ::: "memory")

// ---------------- reduction helper ----------------
__device__ __forceinline__ float block_sum(float v, float* sred) {
    int lane = threadIdx.x & 31, w = threadIdx.x >> 5;
    #pragma unroll
    for (int o = 16; o > 0; o >>= 1) v += __shfl_down_sync(FULLMASK, v, o);
    if (lane == 0) sred[w] = v;
    __syncthreads();
    if (w == 0) {
        v = (lane < (int)(blockDim.x >> 5)) ? sred[lane] : 0.f;
        #pragma unroll
        for (int o = 16; o > 0; o >>= 1) v += __shfl_down_sync(FULLMASK, v, o);
    }
    return v;  // valid in thread 0
}

#define FMA4(ACC, J, V, W4)                         \
    do {                                            \
        ACC[4*(J)+0] = fmaf(V, (W4).x, ACC[4*(J)+0]); \
        ACC[4*(J)+1] = fmaf(V, (W4).y, ACC[4*(J)+1]); \
        ACC[4*(J)+2] = fmaf(V, (W4).z, ACC[4*(J)+2]); \
        ACC[4*(J)+3] = fmaf(V, (W4).w, ACC[4*(J)+3]); \
    } while (0)

// transposed-conv tap, oc-pair packing. Even outputs: w1*v_j. Odd: w2*v_j + w0*v_{j+1}.
__device__ __forceinline__ void ptap(float4 f, float v4,
                                     const ull* w1p, const ull* w2p, const ull* w0p,
                                     ull* ae, ull* ao) {
    ull d0 = pk2(f.x, f.x), d1 = pk2(f.y, f.y), d2 = pk2(f.z, f.z), d3 = pk2(f.w, f.w);
    ull d4 = pk2(v4, v4);
    ulonglong2 A = *(const ulonglong2*)w1p, B = *(const ulonglong2*)(w1p + 2);
    ulonglong2 C = *(const ulonglong2*)w2p, D = *(const ulonglong2*)(w2p + 2);
    ulonglong2 E = *(const ulonglong2*)w0p, F = *(const ulonglong2*)(w0p + 2);
    ull W1[4] = {A.x, A.y, B.x, B.y};
    ull W2[4] = {C.x, C.y, D.x, D.y};
    ull W0[4] = {E.x, E.y, F.x, F.y};
    #pragma unroll
    for (int p = 0; p < 4; p++) {
        ae[0*4+p] = ffma2(d0, W1[p], ae[0*4+p]);
        ae[1*4+p] = ffma2(d1, W1[p], ae[1*4+p]);
        ae[2*4+p] = ffma2(d2, W1[p], ae[2*4+p]);
        ae[3*4+p] = ffma2(d3, W1[p], ae[3*4+p]);
        ao[0*4+p] = ffma2(d1, W0[p], ffma2(d0, W2[p], ao[0*4+p]));
        ao[1*4+p] = ffma2(d2, W0[p], ffma2(d1, W2[p], ao[1*4+p]));
        ao[2*4+p] = ffma2(d3, W0[p], ffma2(d2, W2[p], ao[2*4+p]));
        ao[3*4+p] = ffma2(d4, W0[p], ffma2(d3, W2[p], ao[3*4+p]));
    }
}

// ---------------- dummy: shifts the ncu -s/-c capture window onto k_dec2 -------------
__global__ void k_shift() {}

// ---------------- enc1: conv 3->32, k3 s2 p1, ReLU (P=2 px, oc-pair) ----------------
__global__ void __launch_bounds__(256) k_enc1(const float* __restrict__ x,
                                              const float* __restrict__ w,
                                              const float* __restrict__ bias) {
    __shared__ __align__(16) ull s_wp[432];   // [t = ic*9+kh*3+kw][16 ocp]
    __shared__ ull s_bd[16];
    for (int i = threadIdx.x; i < 432; i += 256) {
        int ocp = i & 15, t = i >> 4;
        s_wp[i] = pk2(w[(2 * ocp) * 27 + t], w[(2 * ocp + 1) * 27 + t]);
    }
    if (threadIdx.x < 16) s_bd[threadIdx.x] = pk2(bias[2*threadIdx.x], bias[2*threadIdx.x+1]);
    __syncthreads();

    int tid = blockIdx.x * 256 + threadIdx.x;      // 64*128*64 threads
    int j = tid & 63, oh = (tid >> 6) & 127, b = tid >> 13;
    int lane = threadIdx.x & 31;

    ull a0[16], a1[16];
    #pragma unroll
    for (int p = 0; p < 16; p++) { a0[p] = s_bd[p]; a1[p] = s_bd[p]; }

    #pragma unroll
    for (int ic = 0; ic < 3; ic++) {
        const float* xp = x + (size_t)(b * 3 + ic) * 65536;
        #pragma unroll
        for (int kh = 0; kh < 3; kh++) {
            int ih = 2 * oh + kh - 1;
            bool okh = (unsigned)ih < 256u;
            const float* row = xp + ih * 256 + 4 * j;
            float4 f = okh ? *(const float4*)row : z4();
            float vL = __shfl_up_sync(FULLMASK, f.w, 1);
            if (lane == 0) vL = (okh && j > 0) ? row[-1] : 0.f;
            ull dL = pk2(vL, vL), dx = pk2(f.x, f.x), dy = pk2(f.y, f.y);
            ull dz = pk2(f.z, f.z), dw_ = pk2(f.w, f.w);
            const ull* wb = s_wp + (ic * 9 + kh * 3) * 16;
            #pragma unroll
            for (int kw = 0; kw < 3; kw++) {
                ull da = (kw == 0) ? dL : (kw == 1) ? dx : dy;
                ull db = (kw == 0) ? dy : (kw == 1) ? dz : dw_;
                const ull* wk = wb + kw * 16;
                #pragma unroll
                for (int p = 0; p < 16; p += 2) {
                    ulonglong2 wp2 = *(const ulonglong2*)(wk + p);
                    a0[p]     = ffma2(da, wp2.x, a0[p]);
                    a0[p + 1] = ffma2(da, wp2.y, a0[p + 1]);
                    a1[p]     = ffma2(db, wp2.x, a1[p]);
                    a1[p + 1] = ffma2(db, wp2.y, a1[p + 1]);
                }
            }
        }
    }
    float* op = g_a1 + (size_t)b * 32 * 16384 + oh * 128 + 2 * j;
    #pragma unroll
    for (int p = 0; p < 16; p++) {
        float2 v0 = upk2(a0[p]);
        float2 v1 = upk2(a1[p]);
        float2 e;
        e.x = rl(v0.x); e.y = rl(v1.x); *(float2*)(op + (size_t)(2*p)   * 16384) = e;
        e.x = rl(v0.y); e.y = rl(v1.y); *(float2*)(op + (size_t)(2*p+1) * 16384) = e;
    }
}

// ---------------- enc2: conv 32->64, k3 s2 p1, ReLU (P=8, oc-pair, RR=2) ------------
__global__ void __launch_bounds__(256, 2) k_enc2(const float* __restrict__ w,
                                                 const float* __restrict__ bias) {
    extern __shared__ __align__(16) ull smu[];
    ull* s_w = smu;               // 9216: [kh][ic][kw][32 ocp]
    ull* s_bd = smu + 9216;       // 32
    for (int i = threadIdx.x; i < 9216; i += 256) {
        int ocp = i & 31; int q = i >> 5; int kw = q % 3; int t2 = q / 3;
        int ic = t2 & 31; int kh = t2 >> 5;
        s_w[i] = pk2(w[(2*ocp)     * 288 + ic * 9 + kh * 3 + kw],
                     w[(2*ocp + 1) * 288 + ic * 9 + kh * 3 + kw]);
    }
    if (threadIdx.x < 32) s_bd[threadIdx.x] = pk2(bias[2*threadIdx.x], bias[2*threadIdx.x+1]);
    __syncthreads();

    int tx = threadIdx.x;
    int chunk = tx & 7, ocg = (tx >> 3) & 7, r = tx >> 6;
    int b = blockIdx.x >> 3, rg = blockIdx.x & 7;
    int ocp0 = ocg * 4;
    int ow0 = chunk * 8;

    #pragma unroll 1
    for (int rr = 0; rr < 2; rr++) {
        int oh = rg * 8 + rr * 4 + r;

        ull acc[32];
        #pragma unroll
        for (int p = 0; p < 4; p++) {
            ull bp = s_bd[ocp0 + p];
            #pragma unroll
            for (int owl = 0; owl < 8; owl++) acc[owl*4+p] = bp;
        }

        #pragma unroll 1
        for (int ic = 0; ic < 32; ic++) {
            const float* plane = g_a1 + (size_t)(b * 32 + ic) * 16384;
            #pragma unroll
            for (int kh = 0; kh < 3; kh++) {
                int ih = 2 * oh + kh - 1;
                if ((unsigned)ih >= 128u) continue;
                const float* row = plane + ih * 128 + chunk * 16;
                float4 g0 = *(const float4*)row;
                float4 g1 = *(const float4*)(row + 4);
                float4 g2 = *(const float4*)(row + 8);
                float4 g3 = *(const float4*)(row + 12);
                float vm1 = __shfl_up_sync(FULLMASK, g3.w, 1);
                if (chunk == 0) vm1 = 0.f;
                const ull* wb = s_w + ((kh * 32 + ic) * 3) * 32 + ocp0;
                ulonglong2 wa0 = *(const ulonglong2*)(wb),      wb0 = *(const ulonglong2*)(wb + 2);
                ulonglong2 wa1 = *(const ulonglong2*)(wb + 32), wb1 = *(const ulonglong2*)(wb + 34);
                ulonglong2 wa2 = *(const ulonglong2*)(wb + 64), wb2 = *(const ulonglong2*)(wb + 66);
                ull W0[4] = {wa0.x, wa0.y, wb0.x, wb0.y};
                ull W1[4] = {wa1.x, wa1.y, wb1.x, wb1.y};
                ull W2[4] = {wa2.x, wa2.y, wb2.x, wb2.y};
                float s[17] = {vm1, g0.x, g0.y, g0.z, g0.w, g1.x, g1.y, g1.z, g1.w,
                               g2.x, g2.y, g2.z, g2.w, g3.x, g3.y, g3.z, g3.w};
                #pragma unroll
                for (int owl = 0; owl < 8; owl++) {
                    ull dA = pk2(s[2*owl],     s[2*owl]);
                    ull dB = pk2(s[2*owl + 1], s[2*owl + 1]);
                    ull dC = pk2(s[2*owl + 2], s[2*owl + 2]);
                    #pragma unroll
                    for (int p = 0; p < 4; p++)
                        acc[owl*4+p] = ffma2(dA, W0[p], ffma2(dB, W1[p], ffma2(dC, W2[p], acc[owl*4+p])));
                }
            }
        }

        float* op = g_a2 + ((size_t)(b * 64 + ocg * 8) * 64 + oh) * 64 + ow0;
        #pragma unroll
        for (int p = 0; p < 4; p++) {
            float2 q0 = upk2(acc[0*4+p]), q1 = upk2(acc[1*4+p]), q2 = upk2(acc[2*4+p]), q3 = upk2(acc[3*4+p]);
            float2 q4 = upk2(acc[4*4+p]), q5 = upk2(acc[5*4+p]), q6 = upk2(acc[6*4+p]), q7 = upk2(acc[7*4+p]);
            float* d0 = op + (size_t)(2*p) * 4096;
            float* d1 = d0 + 4096;
            *(float4*)d0       = make_float4(rl(q0.x), rl(q1.x), rl(q2.x), rl(q3.x));
            *(float4*)(d0 + 4) = make_float4(rl(q4.x), rl(q5.x), rl(q6.x), rl(q7.x));
            *(float4*)d1       = make_float4(rl(q0.y), rl(q1.y), rl(q2.y), rl(q3.y));
            *(float4*)(d1 + 4) = make_float4(rl(q4.y), rl(q5.y), rl(q6.y), rl(q7.y));
        }
    }
}

// ---------------- enc3 (1x1, 64->16) + VQ + q-loss (R11 scalar scan) -----------------
__global__ void __launch_bounds__(256) k_enc3_vq(const float* __restrict__ w3,
                                                 const float* __restrict__ b3,
                                                 const float* __restrict__ cb) {
    __shared__ __align__(16) float s_w[64 * 16];
    __shared__ float s_b[16];
    __shared__ __align__(16) float s_cb[512 * 16];
    __shared__ float s_cn[512];
    __shared__ float sred[32];

    for (int i = threadIdx.x; i < 1024; i += 256) {
        int d = i & 15, ic = i >> 4;
        s_w[i] = w3[d * 64 + ic];
    }
    if (threadIdx.x < 16) s_b[threadIdx.x] = b3[threadIdx.x];
    for (int i = threadIdx.x; i < 8192; i += 256) s_cb[i] = cb[i];
    __syncthreads();
    for (int j = threadIdx.x; j < 512; j += 256) {
        float s = 0.f;
        #pragma unroll
        for (int d = 0; d < 16; d++) { float c = s_cb[j * 16 + d]; s = fmaf(c, c, s); }
        s_cn[j] = s;
    }
    __syncthreads();

    int tid = blockIdx.x * 256 + threadIdx.x;
    int p = tid & 4095, b = tid >> 12;

    float z[16];
    #pragma unroll
    for (int d = 0; d < 16; d++) z[d] = s_b[d];
    const float* ap = g_a2 + (size_t)b * 64 * 4096 + p;
    #pragma unroll 8
    for (int ic = 0; ic < 64; ic++) {
        float v = ap[ic * 4096];
        const float4* wp = (const float4*)&s_w[ic * 16];
        #pragma unroll
        for (int j = 0; j < 4; j++) { float4 w4 = wp[j]; FMA4(z, j, v, w4); }
    }

    int best = 0; float bd = 3.4e38f;
    for (int j = 0; j < 512; j++) {
        const float4* cp = (const float4*)&s_cb[j * 16];
        float dot = 0.f;
        #pragma unroll
        for (int q4 = 0; q4 < 4; q4++) {
            float4 c4 = cp[q4];
            dot = fmaf(z[4*q4+0], c4.x, dot);
            dot = fmaf(z[4*q4+1], c4.y, dot);
            dot = fmaf(z[4*q4+2], c4.z, dot);
            dot = fmaf(z[4*q4+3], c4.w, dot);
        }
        float dist = s_cn[j] - 2.f * dot;
        if (dist < bd) { bd = dist; best = j; }
    }

    float sq = 0.f;
    float* qp = g_q + (size_t)b * 16 * 4096 + p;
    #pragma unroll
    for (int d = 0; d < 16; d++) {
        float qv = s_cb[best * 16 + d];
        float df = qv - z[d];
        sq = fmaf(df, df, sq);
        qp[d * 4096] = qv;
    }
    float bs = block_sum(sq, sred);
    if (threadIdx.x == 0) g_pvq[blockIdx.x] = bs;
}

// ---------------- dec1: convT 16->64 (cp.async double-buffered, RR=4, grid 1024) -----
__device__ __forceinline__ void dec1_stage(float* sbuf, int b, int Rbase, int nr, int tid) {
    int nf4 = 16 * nr * 16;
    for (int i = tid; i < nf4; i += 256) {
        int c4 = i & 15; int q = i >> 4; int row = q % nr; int ic = q / nr;
        int gr = Rbase + row;
        float* dst = sbuf + (ic * nr + row) * 68 + c4 * 4;
        if (gr < 64) cpa16(dst, g_q + ((size_t)b * 16 + ic) * 4096 + gr * 64 + c4 * 4);
        else *(float4*)dst = z4();
    }
}

__global__ void __launch_bounds__(256, 2) k_dec1(const float* __restrict__ w,
                                                 const float* __restrict__ bias) {
    extern __shared__ __align__(16) ull smu[];
    ull* s_w1 = smu;              // [kh][ic][32 ocp]
    ull* s_w2 = smu + 1536;
    ull* s_w0 = smu + 3072;
    ull* s_bd = smu + 4608;       // 32
    float* s_in = (float*)(smu + 4640);   // 2 x 3264 floats
    for (int i = threadIdx.x; i < 1536; i += 256) {
        int ocp = i & 31, ic = (i >> 5) & 15, kh = i >> 9;
        const float* wa = w + ((ic * 64 + 2 * ocp) * 3 + kh) * 3;
        const float* wb = w + ((ic * 64 + 2 * ocp + 1) * 3 + kh) * 3;
        s_w1[i] = pk2(wa[1], wb[1]);
        s_w2[i] = pk2(wa[2], wb[2]);
        s_w0[i] = pk2(wa[0], wb[0]);
    }
    if (threadIdx.x < 32) s_bd[threadIdx.x] = pk2(bias[2*threadIdx.x], bias[2*threadIdx.x+1]);
    for (int i = threadIdx.x; i < 6528; i += 256) s_in[i] = 0.f;
    __syncthreads();

    int tx = threadIdx.x;
    int chunk = tx & 15, ocg = (tx >> 4) & 7, r = tx >> 7;
    int bi = blockIdx.x;
    int b = bi >> 4, rem = bi & 15, ph = rem >> 3, rg = rem & 7;
    int ocp0 = ocg * 4;
    int ow0 = chunk * 8;
    int nr = ph ? 3 : 2;

    dec1_stage(s_in, b, rg * 8, nr, tx); CP_COMMIT();

    #pragma unroll 1
    for (int rr = 0; rr < 4; rr++) {
        int buf = rr & 1;
        if (rr < 3) {
            dec1_stage(s_in + (buf ^ 1) * 3264, b, rg * 8 + (rr + 1) * 2, nr, tx);
            CP_COMMIT(); CP_WAIT1();
        } else CP_WAIT0();
        __syncthreads();

        int R = rg * 8 + rr * 2 + r;
        int oh = 2 * R + ph;
        const float* bufp = s_in + buf * 3264;

        ull ae[16], ao[16];
        #pragma unroll
        for (int p = 0; p < 4; p++) {
            ull bp = s_bd[ocp0 + p];
            ae[p] = bp; ae[4+p] = bp; ae[8+p] = bp; ae[12+p] = bp;
            ao[p] = bp; ao[4+p] = bp; ao[8+p] = bp; ao[12+p] = bp;
        }

        if (ph == 0) {
            #pragma unroll 4
            for (int ic = 0; ic < 16; ic++) {
                const float* rp = bufp + (ic * 2 + r) * 68 + chunk * 4;
                float4 f = *(const float4*)rp; float v4 = rp[4];
                int t0 = (16 + ic) * 32 + ocp0;
                ptap(f, v4, s_w1 + t0, s_w2 + t0, s_w0 + t0, ae, ao);
            }
        } else {
            #pragma unroll 2
            for (int ic = 0; ic < 16; ic++) {
                const float* rpA = bufp + (ic * 3 + r) * 68 + chunk * 4;
                const float* rpB = rpA + 68;
                float4 fa = *(const float4*)rpA; float va = rpA[4];
                float4 fb = *(const float4*)rpB; float vb = rpB[4];
                int ta = (32 + ic) * 32 + ocp0;   // kh=2 @ R
                int tb = ic * 32 + ocp0;          // kh=0 @ R+1
                ptap(fa, va, s_w1 + ta, s_w2 + ta, s_w0 + ta, ae, ao);
                ptap(fb, vb, s_w1 + tb, s_w2 + tb, s_w0 + tb, ae, ao);
            }
        }

        float* op = g_d1 + ((size_t)(b * 64 + ocg * 8) * 128 + oh) * 128 + ow0;
        #pragma unroll
        for (int p = 0; p < 4; p++) {
            float2 e0 = upk2(ae[p]), e1 = upk2(ae[4+p]), e2 = upk2(ae[8+p]), e3 = upk2(ae[12+p]);
            float2 q0 = upk2(ao[p]), q1 = upk2(ao[4+p]), q2 = upk2(ao[8+p]), q3 = upk2(ao[12+p]);
            float* d0 = op + (size_t)(2*p) * 16384;
            float* d1 = d0 + 16384;
            *(float4*)d0       = make_float4(rl(e0.x), rl(q0.x), rl(e1.x), rl(q1.x));
            *(float4*)(d0 + 4) = make_float4(rl(e2.x), rl(q2.x), rl(e3.x), rl(q3.x));
            *(float4*)d1       = make_float4(rl(e0.y), rl(q0.y), rl(e1.y), rl(q1.y));
            *(float4*)(d1 + 4) = make_float4(rl(e2.y), rl(q2.y), rl(e3.y), rl(q3.y));
        }
        __syncthreads();
    }
}

// ---------------- dec2: convT 64->32 (oc-pair, direct LDG, RR=4, 3 CTAs/SM) ----------
// block: chunk(32) x ocg(4) x r(2) = 256. grid: 64b * 2ph * 16rg = 2048.
__global__ void __launch_bounds__(256, 3) k_dec2(const float* __restrict__ w,
                                                 const float* __restrict__ bias) {
    extern __shared__ __align__(16) ull smu[];
    ull* s_w1 = smu;              // [kh][ic][16 ocp] 3072 each
    ull* s_w2 = smu + 3072;
    ull* s_w0 = smu + 6144;
    ull* s_bd = smu + 9216;       // 16
    for (int i = threadIdx.x; i < 3072; i += 256) {
        int ocp = i & 15, ic = (i >> 4) & 63, kh = i >> 10;
        const float* wa = w + ((ic * 32 + 2 * ocp) * 3 + kh) * 3;       // dec_w2 [64][32][3][3]
        const float* wb = w + ((ic * 32 + 2 * ocp + 1) * 3 + kh) * 3;
        s_w1[i] = pk2(wa[1], wb[1]);
        s_w2[i] = pk2(wa[2], wb[2]);
        s_w0[i] = pk2(wa[0], wb[0]);
    }
    if (threadIdx.x < 16) s_bd[threadIdx.x] = pk2(bias[2*threadIdx.x], bias[2*threadIdx.x+1]);
    __syncthreads();

    int tx = threadIdx.x;
    int chunk = tx & 31, ocg = (tx >> 5) & 3, r = tx >> 7;
    int bi = blockIdx.x;
    int b = bi >> 5, rem = bi & 31, ph = rem >> 4, rg = rem & 15;
    int ocp0 = ocg * 4;
    int ow0 = chunk * 8;
    const float* base = g_d1 + (size_t)b * 64 * 16384 + chunk * 4;
    bool edge = (chunk < 31);

    #pragma unroll 1
    for (int rr = 0; rr < 4; rr++) {
        int R = rg * 8 + rr * 2 + r;
        int oh = 2 * R + ph;

        ull ae[16], ao[16];
        #pragma unroll
        for (int p = 0; p < 4; p++) {
            ull bp = s_bd[ocp0 + p];
            ae[p] = bp; ae[4+p] = bp; ae[8+p] = bp; ae[12+p] = bp;
            ao[p] = bp; ao[4+p] = bp; ao[8+p] = bp; ao[12+p] = bp;
        }

        if (ph == 0) {             // single tap kh=1 @ row R; ic-unroll 2
            const float* p0 = base + R * 128;
            #pragma unroll 1
            for (int ic = 0; ic < 64; ic += 2) {
                float4 f0 = *(const float4*)(p0 + (size_t)(ic + 0) * 16384);
                float4 f1 = *(const float4*)(p0 + (size_t)(ic + 1) * 16384);
                float v0 = __shfl_down_sync(FULLMASK, f0.x, 1); if (!edge) v0 = 0.f;
                float v1 = __shfl_down_sync(FULLMASK, f1.x, 1); if (!edge) v1 = 0.f;
                int t0 = (64 + ic) * 16 + ocp0;
                ptap(f0, v0, s_w1 + t0,      s_w2 + t0,      s_w0 + t0,      ae, ao);
                ptap(f1, v1, s_w1 + t0 + 16, s_w2 + t0 + 16, s_w0 + t0 + 16, ae, ao);
            }
        } else {                   // taps kh=2 @ R, kh=0 @ R+1; ic-unroll 1
            bool ok = (R + 1 < 128);
            const float* pa = base + R * 128;
            const float* pb = base + (R + 1) * 128;
            #pragma unroll 1
            for (int ic = 0; ic < 64; ic++) {
                float4 fa = *(const float4*)(pa + (size_t)ic * 16384);
                float4 fb = ok ? *(const float4*)(pb + (size_t)ic * 16384) : z4();
                float va = __shfl_down_sync(FULLMASK, fa.x, 1); if (!edge) va = 0.f;
                float vb = __shfl_down_sync(FULLMASK, fb.x, 1); if (!edge) vb = 0.f;
                int ta = (128 + ic) * 16 + ocp0;   // kh=2
                int tb = ic * 16 + ocp0;           // kh=0
                ptap(fa, va, s_w1 + ta, s_w2 + ta, s_w0 + ta, ae, ao);
                ptap(fb, vb, s_w1 + tb, s_w2 + tb, s_w0 + tb, ae, ao);
            }
        }

        float* op = g_d2 + ((size_t)(b * 32 + ocg * 8) * 256 + oh) * 256 + ow0;
        #pragma unroll
        for (int p = 0; p < 4; p++) {
            float2 e0 = upk2(ae[p]), e1 = upk2(ae[4+p]), e2 = upk2(ae[8+p]), e3 = upk2(ae[12+p]);
            float2 q0 = upk2(ao[p]), q1 = upk2(ao[4+p]), q2 = upk2(ao[8+p]), q3 = upk2(ao[12+p]);
            float* d0 = op + (size_t)(2*p) * 65536;
            float* d1 = d0 + 65536;
            *(float4*)d0       = make_float4(rl(e0.x), rl(q0.x), rl(e1.x), rl(q1.x));
            *(float4*)(d0 + 4) = make_float4(rl(e2.x), rl(q2.x), rl(e3.x), rl(q3.x));
            *(float4*)d1       = make_float4(rl(e0.y), rl(q0.y), rl(e1.y), rl(q1.y));
            *(float4*)(d1 + 4) = make_float4(rl(e2.y), rl(q2.y), rl(e3.y), rl(q3.y));
        }
    }
}

// ---------------- dec3: convT 32->3 s1 p1 + fused MSE (unchanged) --------------------
__global__ void __launch_bounds__(256) k_dec3_mse(const float* __restrict__ w,
                                                  const float* __restrict__ bias,
                                                  const float* __restrict__ x) {
    __shared__ __align__(16) ull s_wd[864];
    __shared__ ull s_bd[3];
    __shared__ float sred[32];
    for (int i = threadIdx.x; i < 864; i += 256) {
        int oc = i % 3; int t = i / 3; int kw = t % 3; t /= 3; int kh = t % 3; int ic = t / 3;
        float wv = w[ic * 27 + oc * 9 + (2 - kh) * 3 + (2 - kw)];
        s_wd[i] = pk2(wv, wv);
    }
    if (threadIdx.x < 3) { float bv = bias[threadIdx.x]; s_bd[threadIdx.x] = pk2(bv, bv); }
    __syncthreads();

    int tx = threadIdx.x;
    int chunk = tx & 31, r = tx >> 5;
    int b = blockIdx.x >> 5, rg = blockIdx.x & 31;
    int oh = rg * 8 + r;
    int ow0 = chunk * 8;

    bool ok0 = (oh > 0), ok2 = (oh < 255);
    bool eL = (chunk != 0), eR = (chunk != 31);

    ull acc[12];
    #pragma unroll
    for (int oc = 0; oc < 3; oc++) {
        ull bp = s_bd[oc];
        acc[oc*4+0] = bp; acc[oc*4+1] = bp; acc[oc*4+2] = bp; acc[oc*4+3] = bp;
    }

    #pragma unroll 1
    for (int ic = 0; ic < 32; ic++) {
        const float* rowm = g_d2 + (size_t)(b * 32 + ic) * 65536 + (oh - 1) * 256 + ow0;
        float4 m0 = ok0 ? *(const float4*)rowm       : z4();
        float4 m1 = ok0 ? *(const float4*)(rowm + 4) : z4();
        float4 c0 = *(const float4*)(rowm + 256);
        float4 c1 = *(const float4*)(rowm + 260);
        float4 b0 = ok2 ? *(const float4*)(rowm + 512) : z4();
        float4 b1 = ok2 ? *(const float4*)(rowm + 516) : z4();
        float mm1 = __shfl_up_sync(FULLMASK, m1.w, 1);   if (!eL) mm1 = 0.f;
        float cm1 = __shfl_up_sync(FULLMASK, c1.w, 1);   if (!eL) cm1 = 0.f;
        float bm1 = __shfl_up_sync(FULLMASK, b1.w, 1);   if (!eL) bm1 = 0.f;
        float m8  = __shfl_down_sync(FULLMASK, m0.x, 1); if (!eR) m8 = 0.f;
        float c8  = __shfl_down_sync(FULLMASK, c0.x, 1); if (!eR) c8 = 0.f;
        float b8  = __shfl_down_sync(FULLMASK, b0.x, 1); if (!eR) b8 = 0.f;

        const ull* wp = s_wd + ic * 27;
        #pragma unroll
        for (int kh = 0; kh < 3; kh++) {
            float4 f0 = (kh == 0) ? m0 : (kh == 1) ? c0 : b0;
            float4 f1 = (kh == 0) ? m1 : (kh == 1) ? c1 : b1;
            float vm1 = (kh == 0) ? mm1 : (kh == 1) ? cm1 : bm1;
            float v8  = (kh == 0) ? m8  : (kh == 1) ? c8  : b8;
            ull A0 = pk2(f0.x, f0.y), A1 = pk2(f0.z, f0.w), A2 = pk2(f1.x, f1.y), A3 = pk2(f1.z, f1.w);
            ull O0 = pk2(vm1, f0.x), O1 = pk2(f0.y, f0.z), O2 = pk2(f0.w, f1.x),
                O3 = pk2(f1.y, f1.z), O4 = pk2(f1.w, v8);
            const ull* wk = wp + kh * 9;
            #pragma unroll
            for (int oc = 0; oc < 3; oc++) {
                ull w0 = wk[oc], w1 = wk[3 + oc], w2 = wk[6 + oc];
                acc[oc*4+0] = ffma2(O0, w0, ffma2(A0, w1, ffma2(O1, w2, acc[oc*4+0])));
                acc[oc*4+1] = ffma2(O1, w0, ffma2(A1, w1, ffma2(O2, w2, acc[oc*4+1])));
                acc[oc*4+2] = ffma2(O2, w0, ffma2(A2, w1, ffma2(O3, w2, acc[oc*4+2])));
                acc[oc*4+3] = ffma2(O3, w0, ffma2(A3, w1, ffma2(O4, w2, acc[oc*4+3])));
            }
        }
    }

    const float* xp = x + (size_t)b * 3 * 65536 + oh * 256 + ow0;
    float sq = 0.f;
    #pragma unroll
    for (int oc = 0; oc < 3; oc++) {
        float4 x0 = *(const float4*)(xp + (size_t)oc * 65536);
        float4 x1 = *(const float4*)(xp + (size_t)oc * 65536 + 4);
        float2 p0 = upk2(acc[oc*4+0]), p1 = upk2(acc[oc*4+1]);
        float2 p2 = upk2(acc[oc*4+2]), p3 = upk2(acc[oc*4+3]);
        float e;
        e = p0.x - x0.x; sq = fmaf(e, e, sq);
        e = p0.y - x0.y; sq = fmaf(e, e, sq);
        e = p1.x - x0.z; sq = fmaf(e, e, sq);
        e = p1.y - x0.w; sq = fmaf(e, e, sq);
        e = p2.x - x1.x; sq = fmaf(e, e, sq);
        e = p2.y - x1.y; sq = fmaf(e, e, sq);
        e = p3.x - x1.z; sq = fmaf(e, e, sq);
        e = p3.y - x1.w; sq = fmaf(e, e, sq);
    }
    float bs = block_sum(sq, sred);
    if (threadIdx.x == 0) g_pmse[blockIdx.x] = bs;
}

// ---------------- deterministic final reduction ----------------
__global__ void k_final(float* __restrict__ out) {
    __shared__ double sd[256];
    double s1 = 0.0, s2 = 0.0;
    for (int i = threadIdx.x; i < 1024; i += 256) s1 += (double)g_pvq[i];
    for (int i = threadIdx.x; i < 2048; i += 256) s2 += (double)g_pmse[i];
    sd[threadIdx.x] = s1; __syncthreads();
    for (int o = 128; o > 0; o >>= 1) {
        if ((int)threadIdx.x < o) sd[threadIdx.x] += sd[threadIdx.x + o];
        __syncthreads();
    }
    double vq = sd[0]; __syncthreads();
    sd[threadIdx.x] = s2; __syncthreads();
    for (int o = 128; o > 0; o >>= 1) {
        if ((int)threadIdx.x < o) sd[threadIdx.x] += sd[threadIdx.x + o];
        __syncthreads();
    }
    if (threadIdx.x == 0) {
        double mq = vq / 4194304.0;
        double mr = sd[0] / 12582912.0;
        out[0] = (float)(1.25 * mq);
        out[1] = (float)mr;
        out[2] = (float)mr;
    }
}

// ---------------- launch ----------------
extern "C" void kernel_launch(void* const* d_in, const int* in_sizes, int n_in,
                              void* d_out, int out_size) {
    const float* x   = (const float*)d_in[0];
    const float* ew1 = (const float*)d_in[1];
    const float* eb1 = (const float*)d_in[2];
    const float* ew2 = (const float*)d_in[3];
    const float* eb2 = (const float*)d_in[4];
    const float* ew3 = (const float*)d_in[5];
    const float* eb3 = (const float*)d_in[6];
    const float* cb  = (const float*)d_in[7];
    const float* dw1 = (const float*)d_in[8];
    const float* db1 = (const float*)d_in[9];
    const float* dw2 = (const float*)d_in[10];
    const float* db2 = (const float*)d_in[11];
    const float* dw3 = (const float*)d_in[12];
    const float* db3 = (const float*)d_in[13];
    float* out = (float*)d_out;

    const int smem_enc2 = (9216 + 32) * 8;           // 73984 B
    const int smem_dec1 = 4640 * 8 + 6528 * 4;       // 63232 B
    const int smem_dec2 = (9216 + 16) * 8;           // 73856 B
    cudaFuncSetAttribute(k_enc2, cudaFuncAttributeMaxDynamicSharedMemorySize, smem_enc2);
    cudaFuncSetAttribute(k_dec1, cudaFuncAttributeMaxDynamicSharedMemorySize, smem_dec1);
    cudaFuncSetAttribute(k_dec2, cudaFuncAttributeMaxDynamicSharedMemorySize, smem_dec2);

    k_enc1    <<<2048, 256>>>(x, ew1, eb1);
    k_enc2    <<<512, 256, smem_enc2>>>(ew2, eb2);
    k_enc3_vq <<<1024, 256>>>(ew3, eb3, cb);
    k_dec1    <<<1024, 256, smem_dec1>>>(dw1, db1);
    k_shift   <<<1, 32>>>();                          // shifts ncu capture onto k_dec2
    k_dec2    <<<2048, 256, smem_dec2>>>(dw2, db2);
    k_dec3_mse<<<2048, 256>>>(dw3, db3, x);
    k_final   <<<1, 256>>>(out);
}

// round 16
// speedup vs baseline: 1.8054x; 1.8054x over previous
#include <cuda_runtime.h>

typedef unsigned long long ull;

// ---------------- scratch (device globals; no allocation allowed) ----------------
static __device__ __align__(16) float g_a1[64*32*128*128];          // enc1 out
static __device__ __align__(16) float g_a2[64*64*64*64];            // enc2 out
static __device__ __align__(16) float g_q [64*16*64*64];            // quantized (decoder input)
static __device__ __align__(16) float g_d1[64*64*128*128];          // dec1 out
static __device__ __align__(16) float g_d2[64*32*256*256];          // dec2 out
static __device__ float g_pvq [1024];                               // per-block VQ sq-sum
static __device__ float g_pmse[2048];                               // per-block recon sq-sum

#define FULLMASK 0xffffffffu

// ---------------- f32x2 helpers ----------------
__device__ __forceinline__ ull pk2(float lo, float hi) {
    ull r;
    asm("mov.b64 %0, {%1, %2};" : "=l"(r)
        : "r"(__float_as_uint(lo)), "r"(__float_as_uint(hi)));
    return r;
}
__device__ __forceinline__ float2 upk2(ull p) {
    unsigned int a, b;
    asm("mov.b64 {%0, %1}, %2;" : "=r"(a), "=r"(b) : "l"(p));
    return make_float2(__uint_as_float(a), __uint_as_float(b));
}
__device__ __forceinline__ ull ffma2(ull a, ull b, ull c) {
    ull d;
    asm("fma.rn.f32x2 %0, %1, %2, %3;" : "=l"(d) : "l"(a), "l"(b), "l"(c));
    return d;
}
__device__ __forceinline__ float4 z4() { return make_float4(0.f, 0.f, 0.f, 0.f); }
__device__ __forceinline__ float rl(float v) { return fmaxf(v, 0.f); }

// ---------------- cp.async helpers ----------------
__device__ __forceinline__ void cpa16(void* smem_dst, const void* gsrc) {
    unsigned sa = (unsigned)__cvta_generic_to_shared(smem_dst);
    asm volatile("cp.async.ca.shared.global [%0], [%1], 16;" :: "r"(sa), "l"(gsrc));
}
#define CP_COMMIT() asm volatile("cp.async.commit_group;" ::: "memory")
#define CP_WAIT1()  asm volatile("cp.async.wait_group 1;" ::: "memory")
#define CP_WAIT0()  asm volatile("cp.async.wait_group 0;" ::: "memory")

// ---------------- reduction helper ----------------
__device__ __forceinline__ float block_sum(float v, float* sred) {
    int lane = threadIdx.x & 31, w = threadIdx.x >> 5;
    #pragma unroll
    for (int o = 16; o > 0; o >>= 1) v += __shfl_down_sync(FULLMASK, v, o);
    if (lane == 0) sred[w] = v;
    __syncthreads();
    if (w == 0) {
        v = (lane < (int)(blockDim.x >> 5)) ? sred[lane] : 0.f;
        #pragma unroll
        for (int o = 16; o > 0; o >>= 1) v += __shfl_down_sync(FULLMASK, v, o);
    }
    return v;  // valid in thread 0
}

#define FMA4(ACC, J, V, W4)                         \
    do {                                            \
        ACC[4*(J)+0] = fmaf(V, (W4).x, ACC[4*(J)+0]); \
        ACC[4*(J)+1] = fmaf(V, (W4).y, ACC[4*(J)+1]); \
        ACC[4*(J)+2] = fmaf(V, (W4).z, ACC[4*(J)+2]); \
        ACC[4*(J)+3] = fmaf(V, (W4).w, ACC[4*(J)+3]); \
    } while (0)

// transposed-conv tap, oc-pair packing. Even outputs: w1*v_j. Odd: w2*v_j + w0*v_{j+1}.
__device__ __forceinline__ void ptap(float4 f, float v4,
                                     const ull* w1p, const ull* w2p, const ull* w0p,
                                     ull* ae, ull* ao) {
    ull d0 = pk2(f.x, f.x), d1 = pk2(f.y, f.y), d2 = pk2(f.z, f.z), d3 = pk2(f.w, f.w);
    ull d4 = pk2(v4, v4);
    ulonglong2 A = *(const ulonglong2*)w1p, B = *(const ulonglong2*)(w1p + 2);
    ulonglong2 C = *(const ulonglong2*)w2p, D = *(const ulonglong2*)(w2p + 2);
    ulonglong2 E = *(const ulonglong2*)w0p, F = *(const ulonglong2*)(w0p + 2);
    ull W1[4] = {A.x, A.y, B.x, B.y};
    ull W2[4] = {C.x, C.y, D.x, D.y};
    ull W0[4] = {E.x, E.y, F.x, F.y};
    #pragma unroll
    for (int p = 0; p < 4; p++) {
        ae[0*4+p] = ffma2(d0, W1[p], ae[0*4+p]);
        ae[1*4+p] = ffma2(d1, W1[p], ae[1*4+p]);
        ae[2*4+p] = ffma2(d2, W1[p], ae[2*4+p]);
        ae[3*4+p] = ffma2(d3, W1[p], ae[3*4+p]);
        ao[0*4+p] = ffma2(d1, W0[p], ffma2(d0, W2[p], ao[0*4+p]));
        ao[1*4+p] = ffma2(d2, W0[p], ffma2(d1, W2[p], ao[1*4+p]));
        ao[2*4+p] = ffma2(d3, W0[p], ffma2(d2, W2[p], ao[2*4+p]));
        ao[3*4+p] = ffma2(d4, W0[p], ffma2(d3, W2[p], ao[3*4+p]));
    }
}

// ---------------- enc1: conv 3->32, k3 s2 p1, ReLU (P=2 px, oc-pair) ----------------
__global__ void __launch_bounds__(256) k_enc1(const float* __restrict__ x,
                                              const float* __restrict__ w,
                                              const float* __restrict__ bias) {
    __shared__ __align__(16) ull s_wp[432];   // [t = ic*9+kh*3+kw][16 ocp]
    __shared__ ull s_bd[16];
    for (int i = threadIdx.x; i < 432; i += 256) {
        int ocp = i & 15, t = i >> 4;
        s_wp[i] = pk2(w[(2 * ocp) * 27 + t], w[(2 * ocp + 1) * 27 + t]);
    }
    if (threadIdx.x < 16) s_bd[threadIdx.x] = pk2(bias[2*threadIdx.x], bias[2*threadIdx.x+1]);
    __syncthreads();

    int tid = blockIdx.x * 256 + threadIdx.x;      // 64*128*64 threads
    int j = tid & 63, oh = (tid >> 6) & 127, b = tid >> 13;
    int lane = threadIdx.x & 31;

    ull a0[16], a1[16];
    #pragma unroll
    for (int p = 0; p < 16; p++) { a0[p] = s_bd[p]; a1[p] = s_bd[p]; }

    #pragma unroll
    for (int ic = 0; ic < 3; ic++) {
        const float* xp = x + (size_t)(b * 3 + ic) * 65536;
        #pragma unroll
        for (int kh = 0; kh < 3; kh++) {
            int ih = 2 * oh + kh - 1;
            bool okh = (unsigned)ih < 256u;
            const float* row = xp + ih * 256 + 4 * j;
            float4 f = okh ? *(const float4*)row : z4();
            float vL = __shfl_up_sync(FULLMASK, f.w, 1);
            if (lane == 0) vL = (okh && j > 0) ? row[-1] : 0.f;
            ull dL = pk2(vL, vL), dx = pk2(f.x, f.x), dy = pk2(f.y, f.y);
            ull dz = pk2(f.z, f.z), dw_ = pk2(f.w, f.w);
            const ull* wb = s_wp + (ic * 9 + kh * 3) * 16;
            #pragma unroll
            for (int kw = 0; kw < 3; kw++) {
                ull da = (kw == 0) ? dL : (kw == 1) ? dx : dy;
                ull db = (kw == 0) ? dy : (kw == 1) ? dz : dw_;
                const ull* wk = wb + kw * 16;
                #pragma unroll
                for (int p = 0; p < 16; p += 2) {
                    ulonglong2 wp2 = *(const ulonglong2*)(wk + p);
                    a0[p]     = ffma2(da, wp2.x, a0[p]);
                    a0[p + 1] = ffma2(da, wp2.y, a0[p + 1]);
                    a1[p]     = ffma2(db, wp2.x, a1[p]);
                    a1[p + 1] = ffma2(db, wp2.y, a1[p + 1]);
                }
            }
        }
    }
    float* op = g_a1 + (size_t)b * 32 * 16384 + oh * 128 + 2 * j;
    #pragma unroll
    for (int p = 0; p < 16; p++) {
        float2 v0 = upk2(a0[p]);
        float2 v1 = upk2(a1[p]);
        float2 e;
        e.x = rl(v0.x); e.y = rl(v1.x); *(float2*)(op + (size_t)(2*p)   * 16384) = e;
        e.x = rl(v0.y); e.y = rl(v1.y); *(float2*)(op + (size_t)(2*p+1) * 16384) = e;
    }
}

// ---------------- enc2: conv 32->64, k3 s2 p1, ReLU (P=8, oc-pair, RR=2) ------------
__global__ void __launch_bounds__(256, 2) k_enc2(const float* __restrict__ w,
                                                 const float* __restrict__ bias) {
    extern __shared__ __align__(16) ull smu[];
    ull* s_w = smu;               // 9216: [kh][ic][kw][32 ocp]
    ull* s_bd = smu + 9216;       // 32
    for (int i = threadIdx.x; i < 9216; i += 256) {
        int ocp = i & 31; int q = i >> 5; int kw = q % 3; int t2 = q / 3;
        int ic = t2 & 31; int kh = t2 >> 5;
        s_w[i] = pk2(w[(2*ocp)     * 288 + ic * 9 + kh * 3 + kw],
                     w[(2*ocp + 1) * 288 + ic * 9 + kh * 3 + kw]);
    }
    if (threadIdx.x < 32) s_bd[threadIdx.x] = pk2(bias[2*threadIdx.x], bias[2*threadIdx.x+1]);
    __syncthreads();

    int tx = threadIdx.x;
    int chunk = tx & 7, ocg = (tx >> 3) & 7, r = tx >> 6;
    int b = blockIdx.x >> 3, rg = blockIdx.x & 7;
    int ocp0 = ocg * 4;
    int ow0 = chunk * 8;

    #pragma unroll 1
    for (int rr = 0; rr < 2; rr++) {
        int oh = rg * 8 + rr * 4 + r;

        ull acc[32];
        #pragma unroll
        for (int p = 0; p < 4; p++) {
            ull bp = s_bd[ocp0 + p];
            #pragma unroll
            for (int owl = 0; owl < 8; owl++) acc[owl*4+p] = bp;
        }

        #pragma unroll 1
        for (int ic = 0; ic < 32; ic++) {
            const float* plane = g_a1 + (size_t)(b * 32 + ic) * 16384;
            #pragma unroll
            for (int kh = 0; kh < 3; kh++) {
                int ih = 2 * oh + kh - 1;
                if ((unsigned)ih >= 128u) continue;
                const float* row = plane + ih * 128 + chunk * 16;
                float4 g0 = *(const float4*)row;
                float4 g1 = *(const float4*)(row + 4);
                float4 g2 = *(const float4*)(row + 8);
                float4 g3 = *(const float4*)(row + 12);
                float vm1 = __shfl_up_sync(FULLMASK, g3.w, 1);
                if (chunk == 0) vm1 = 0.f;
                const ull* wb = s_w + ((kh * 32 + ic) * 3) * 32 + ocp0;
                ulonglong2 wa0 = *(const ulonglong2*)(wb),      wb0 = *(const ulonglong2*)(wb + 2);
                ulonglong2 wa1 = *(const ulonglong2*)(wb + 32), wb1 = *(const ulonglong2*)(wb + 34);
                ulonglong2 wa2 = *(const ulonglong2*)(wb + 64), wb2 = *(const ulonglong2*)(wb + 66);
                ull W0[4] = {wa0.x, wa0.y, wb0.x, wb0.y};
                ull W1[4] = {wa1.x, wa1.y, wb1.x, wb1.y};
                ull W2[4] = {wa2.x, wa2.y, wb2.x, wb2.y};
                float s[17] = {vm1, g0.x, g0.y, g0.z, g0.w, g1.x, g1.y, g1.z, g1.w,
                               g2.x, g2.y, g2.z, g2.w, g3.x, g3.y, g3.z, g3.w};
                #pragma unroll
                for (int owl = 0; owl < 8; owl++) {
                    ull dA = pk2(s[2*owl],     s[2*owl]);
                    ull dB = pk2(s[2*owl + 1], s[2*owl + 1]);
                    ull dC = pk2(s[2*owl + 2], s[2*owl + 2]);
                    #pragma unroll
                    for (int p = 0; p < 4; p++)
                        acc[owl*4+p] = ffma2(dA, W0[p], ffma2(dB, W1[p], ffma2(dC, W2[p], acc[owl*4+p])));
                }
            }
        }

        float* op = g_a2 + ((size_t)(b * 64 + ocg * 8) * 64 + oh) * 64 + ow0;
        #pragma unroll
        for (int p = 0; p < 4; p++) {
            float2 q0 = upk2(acc[0*4+p]), q1 = upk2(acc[1*4+p]), q2 = upk2(acc[2*4+p]), q3 = upk2(acc[3*4+p]);
            float2 q4 = upk2(acc[4*4+p]), q5 = upk2(acc[5*4+p]), q6 = upk2(acc[6*4+p]), q7 = upk2(acc[7*4+p]);
            float* d0 = op + (size_t)(2*p) * 4096;
            float* d1 = d0 + 4096;
            *(float4*)d0       = make_float4(rl(q0.x), rl(q1.x), rl(q2.x), rl(q3.x));
            *(float4*)(d0 + 4) = make_float4(rl(q4.x), rl(q5.x), rl(q6.x), rl(q7.x));
            *(float4*)d1       = make_float4(rl(q0.y), rl(q1.y), rl(q2.y), rl(q3.y));
            *(float4*)(d1 + 4) = make_float4(rl(q4.y), rl(q5.y), rl(q6.y), rl(q7.y));
        }
    }
}

// ---------------- enc3 (1x1, 64->16) + VQ + q-loss (R11 scalar scan) -----------------
__global__ void __launch_bounds__(256) k_enc3_vq(const float* __restrict__ w3,
                                                 const float* __restrict__ b3,
                                                 const float* __restrict__ cb) {
    __shared__ __align__(16) float s_w[64 * 16];
    __shared__ float s_b[16];
    __shared__ __align__(16) float s_cb[512 * 16];
    __shared__ float s_cn[512];
    __shared__ float sred[32];

    for (int i = threadIdx.x; i < 1024; i += 256) {
        int d = i & 15, ic = i >> 4;
        s_w[i] = w3[d * 64 + ic];
    }
    if (threadIdx.x < 16) s_b[threadIdx.x] = b3[threadIdx.x];
    for (int i = threadIdx.x; i < 8192; i += 256) s_cb[i] = cb[i];
    __syncthreads();
    for (int j = threadIdx.x; j < 512; j += 256) {
        float s = 0.f;
        #pragma unroll
        for (int d = 0; d < 16; d++) { float c = s_cb[j * 16 + d]; s = fmaf(c, c, s); }
        s_cn[j] = s;
    }
    __syncthreads();

    int tid = blockIdx.x * 256 + threadIdx.x;
    int p = tid & 4095, b = tid >> 12;

    float z[16];
    #pragma unroll
    for (int d = 0; d < 16; d++) z[d] = s_b[d];
    const float* ap = g_a2 + (size_t)b * 64 * 4096 + p;
    #pragma unroll 8
    for (int ic = 0; ic < 64; ic++) {
        float v = ap[ic * 4096];
        const float4* wp = (const float4*)&s_w[ic * 16];
        #pragma unroll
        for (int j = 0; j < 4; j++) { float4 w4 = wp[j]; FMA4(z, j, v, w4); }
    }

    int best = 0; float bd = 3.4e38f;
    for (int j = 0; j < 512; j++) {
        const float4* cp = (const float4*)&s_cb[j * 16];
        float dot = 0.f;
        #pragma unroll
        for (int q4 = 0; q4 < 4; q4++) {
            float4 c4 = cp[q4];
            dot = fmaf(z[4*q4+0], c4.x, dot);
            dot = fmaf(z[4*q4+1], c4.y, dot);
            dot = fmaf(z[4*q4+2], c4.z, dot);
            dot = fmaf(z[4*q4+3], c4.w, dot);
        }
        float dist = s_cn[j] - 2.f * dot;
        if (dist < bd) { bd = dist; best = j; }
    }

    float sq = 0.f;
    float* qp = g_q + (size_t)b * 16 * 4096 + p;
    #pragma unroll
    for (int d = 0; d < 16; d++) {
        float qv = s_cb[best * 16 + d];
        float df = qv - z[d];
        sq = fmaf(df, df, sq);
        qp[d * 4096] = qv;
    }
    float bs = block_sum(sq, sred);
    if (threadIdx.x == 0) g_pvq[blockIdx.x] = bs;
}

// ---------------- dec1: convT 16->64 (cp.async double-buffered, RR=4, grid 1024) -----
__device__ __forceinline__ void dec1_stage(float* sbuf, int b, int Rbase, int nr, int tid) {
    int nf4 = 16 * nr * 16;
    for (int i = tid; i < nf4; i += 256) {
        int c4 = i & 15; int q = i >> 4; int row = q % nr; int ic = q / nr;
        int gr = Rbase + row;
        float* dst = sbuf + (ic * nr + row) * 68 + c4 * 4;
        if (gr < 64) cpa16(dst, g_q + ((size_t)b * 16 + ic) * 4096 + gr * 64 + c4 * 4);
        else *(float4*)dst = z4();
    }
}

__global__ void __launch_bounds__(256, 2) k_dec1(const float* __restrict__ w,
                                                 const float* __restrict__ bias) {
    extern __shared__ __align__(16) ull smu[];
    ull* s_w1 = smu;              // [kh][ic][32 ocp]
    ull* s_w2 = smu + 1536;
    ull* s_w0 = smu + 3072;
    ull* s_bd = smu + 4608;       // 32
    float* s_in = (float*)(smu + 4640);   // 2 x 3264 floats
    for (int i = threadIdx.x; i < 1536; i += 256) {
        int ocp = i & 31, ic = (i >> 5) & 15, kh = i >> 9;
        const float* wa = w + ((ic * 64 + 2 * ocp) * 3 + kh) * 3;
        const float* wb = w + ((ic * 64 + 2 * ocp + 1) * 3 + kh) * 3;
        s_w1[i] = pk2(wa[1], wb[1]);
        s_w2[i] = pk2(wa[2], wb[2]);
        s_w0[i] = pk2(wa[0], wb[0]);
    }
    if (threadIdx.x < 32) s_bd[threadIdx.x] = pk2(bias[2*threadIdx.x], bias[2*threadIdx.x+1]);
    for (int i = threadIdx.x; i < 6528; i += 256) s_in[i] = 0.f;
    __syncthreads();

    int tx = threadIdx.x;
    int chunk = tx & 15, ocg = (tx >> 4) & 7, r = tx >> 7;
    int bi = blockIdx.x;
    int b = bi >> 4, rem = bi & 15, ph = rem >> 3, rg = rem & 7;
    int ocp0 = ocg * 4;
    int ow0 = chunk * 8;
    int nr = ph ? 3 : 2;

    dec1_stage(s_in, b, rg * 8, nr, tx); CP_COMMIT();

    #pragma unroll 1
    for (int rr = 0; rr < 4; rr++) {
        int buf = rr & 1;
        if (rr < 3) {
            dec1_stage(s_in + (buf ^ 1) * 3264, b, rg * 8 + (rr + 1) * 2, nr, tx);
            CP_COMMIT(); CP_WAIT1();
        } else CP_WAIT0();
        __syncthreads();

        int R = rg * 8 + rr * 2 + r;
        int oh = 2 * R + ph;
        const float* bufp = s_in + buf * 3264;

        ull ae[16], ao[16];
        #pragma unroll
        for (int p = 0; p < 4; p++) {
            ull bp = s_bd[ocp0 + p];
            ae[p] = bp; ae[4+p] = bp; ae[8+p] = bp; ae[12+p] = bp;
            ao[p] = bp; ao[4+p] = bp; ao[8+p] = bp; ao[12+p] = bp;
        }

        if (ph == 0) {
            #pragma unroll 4
            for (int ic = 0; ic < 16; ic++) {
                const float* rp = bufp + (ic * 2 + r) * 68 + chunk * 4;
                float4 f = *(const float4*)rp; float v4 = rp[4];
                int t0 = (16 + ic) * 32 + ocp0;
                ptap(f, v4, s_w1 + t0, s_w2 + t0, s_w0 + t0, ae, ao);
            }
        } else {
            #pragma unroll 2
            for (int ic = 0; ic < 16; ic++) {
                const float* rpA = bufp + (ic * 3 + r) * 68 + chunk * 4;
                const float* rpB = rpA + 68;
                float4 fa = *(const float4*)rpA; float va = rpA[4];
                float4 fb = *(const float4*)rpB; float vb = rpB[4];
                int ta = (32 + ic) * 32 + ocp0;   // kh=2 @ R
                int tb = ic * 32 + ocp0;          // kh=0 @ R+1
                ptap(fa, va, s_w1 + ta, s_w2 + ta, s_w0 + ta, ae, ao);
                ptap(fb, vb, s_w1 + tb, s_w2 + tb, s_w0 + tb, ae, ao);
            }
        }

        float* op = g_d1 + ((size_t)(b * 64 + ocg * 8) * 128 + oh) * 128 + ow0;
        #pragma unroll
        for (int p = 0; p < 4; p++) {
            float2 e0 = upk2(ae[p]), e1 = upk2(ae[4+p]), e2 = upk2(ae[8+p]), e3 = upk2(ae[12+p]);
            float2 q0 = upk2(ao[p]), q1 = upk2(ao[4+p]), q2 = upk2(ao[8+p]), q3 = upk2(ao[12+p]);
            float* d0 = op + (size_t)(2*p) * 16384;
            float* d1 = d0 + 16384;
            *(float4*)d0       = make_float4(rl(e0.x), rl(q0.x), rl(e1.x), rl(q1.x));
            *(float4*)(d0 + 4) = make_float4(rl(e2.x), rl(q2.x), rl(e3.x), rl(q3.x));
            *(float4*)d1       = make_float4(rl(e0.y), rl(q0.y), rl(e1.y), rl(q1.y));
            *(float4*)(d1 + 4) = make_float4(rl(e2.y), rl(q2.y), rl(e3.y), rl(q3.y));
        }
        __syncthreads();
    }
}

// ---------------- dec2: convT 64->32 (oc-pair, direct LDG, RR=4, 2 CTAs/SM) ----------
// block: chunk(32) x ocg(4) x r(2) = 256. grid: 64b * 2ph * 16rg = 2048.
__global__ void __launch_bounds__(256, 2) k_dec2(const float* __restrict__ w,
                                                 const float* __restrict__ bias) {
    extern __shared__ __align__(16) ull smu[];
    ull* s_w1 = smu;              // [kh][ic][16 ocp] 3072 each
    ull* s_w2 = smu + 3072;
    ull* s_w0 = smu + 6144;
    ull* s_bd = smu + 9216;       // 16
    for (int i = threadIdx.x; i < 3072; i += 256) {
        int ocp = i & 15, ic = (i >> 4) & 63, kh = i >> 10;
        const float* wa = w + ((ic * 32 + 2 * ocp) * 3 + kh) * 3;       // dec_w2 [64][32][3][3]
        const float* wb = w + ((ic * 32 + 2 * ocp + 1) * 3 + kh) * 3;
        s_w1[i] = pk2(wa[1], wb[1]);
        s_w2[i] = pk2(wa[2], wb[2]);
        s_w0[i] = pk2(wa[0], wb[0]);
    }
    if (threadIdx.x < 16) s_bd[threadIdx.x] = pk2(bias[2*threadIdx.x], bias[2*threadIdx.x+1]);
    __syncthreads();

    int tx = threadIdx.x;
    int chunk = tx & 31, ocg = (tx >> 5) & 3, r = tx >> 7;
    int bi = blockIdx.x;
    int b = bi >> 5, rem = bi & 31, ph = rem >> 4, rg = rem & 15;
    int ocp0 = ocg * 4;
    int ow0 = chunk * 8;
    const float* base = g_d1 + (size_t)b * 64 * 16384 + chunk * 4;
    bool edge = (chunk < 31);

    #pragma unroll 1
    for (int rr = 0; rr < 4; rr++) {
        int R = rg * 8 + rr * 2 + r;
        int oh = 2 * R + ph;

        ull ae[16], ao[16];
        #pragma unroll
        for (int p = 0; p < 4; p++) {
            ull bp = s_bd[ocp0 + p];
            ae[p] = bp; ae[4+p] = bp; ae[8+p] = bp; ae[12+p] = bp;
            ao[p] = bp; ao[4+p] = bp; ao[8+p] = bp; ao[12+p] = bp;
        }

        if (ph == 0) {             // single tap kh=1 @ row R; ic-unroll 4
            const float* p0 = base + R * 128;
            #pragma unroll 1
            for (int ic = 0; ic < 64; ic += 4) {
                float4 f0 = *(const float4*)(p0 + (size_t)(ic + 0) * 16384);
                float4 f1 = *(const float4*)(p0 + (size_t)(ic + 1) * 16384);
                float4 f2 = *(const float4*)(p0 + (size_t)(ic + 2) * 16384);
                float4 f3 = *(const float4*)(p0 + (size_t)(ic + 3) * 16384);
                float v0 = __shfl_down_sync(FULLMASK, f0.x, 1); if (!edge) v0 = 0.f;
                float v1 = __shfl_down_sync(FULLMASK, f1.x, 1); if (!edge) v1 = 0.f;
                float v2 = __shfl_down_sync(FULLMASK, f2.x, 1); if (!edge) v2 = 0.f;
                float v3 = __shfl_down_sync(FULLMASK, f3.x, 1); if (!edge) v3 = 0.f;
                int t0 = (64 + ic) * 16 + ocp0;
                ptap(f0, v0, s_w1 + t0,      s_w2 + t0,      s_w0 + t0,      ae, ao);
                ptap(f1, v1, s_w1 + t0 + 16, s_w2 + t0 + 16, s_w0 + t0 + 16, ae, ao);
                ptap(f2, v2, s_w1 + t0 + 32, s_w2 + t0 + 32, s_w0 + t0 + 32, ae, ao);
                ptap(f3, v3, s_w1 + t0 + 48, s_w2 + t0 + 48, s_w0 + t0 + 48, ae, ao);
            }
        } else {                   // taps kh=2 @ R, kh=0 @ R+1; ic-unroll 2
            bool ok = (R + 1 < 128);
            const float* pa = base + R * 128;
            const float* pb = base + (R + 1) * 128;
            #pragma unroll 1
            for (int ic = 0; ic < 64; ic += 2) {
                float4 fa0 = *(const float4*)(pa + (size_t)ic * 16384);
                float4 fa1 = *(const float4*)(pa + (size_t)(ic + 1) * 16384);
                float4 fb0 = ok ? *(const float4*)(pb + (size_t)ic * 16384) : z4();
                float4 fb1 = ok ? *(const float4*)(pb + (size_t)(ic + 1) * 16384) : z4();
                float va0 = __shfl_down_sync(FULLMASK, fa0.x, 1); if (!edge) va0 = 0.f;
                float va1 = __shfl_down_sync(FULLMASK, fa1.x, 1); if (!edge) va1 = 0.f;
                float vb0 = __shfl_down_sync(FULLMASK, fb0.x, 1); if (!edge) vb0 = 0.f;
                float vb1 = __shfl_down_sync(FULLMASK, fb1.x, 1); if (!edge) vb1 = 0.f;
                int ta = (128 + ic) * 16 + ocp0;   // kh=2
                int tb = ic * 16 + ocp0;           // kh=0
                ptap(fa0, va0, s_w1 + ta,      s_w2 + ta,      s_w0 + ta,      ae, ao);
                ptap(fb0, vb0, s_w1 + tb,      s_w2 + tb,      s_w0 + tb,      ae, ao);
                ptap(fa1, va1, s_w1 + ta + 16, s_w2 + ta + 16, s_w0 + ta + 16, ae, ao);
                ptap(fb1, vb1, s_w1 + tb + 16, s_w2 + tb + 16, s_w0 + tb + 16, ae, ao);
            }
        }

        float* op = g_d2 + ((size_t)(b * 32 + ocg * 8) * 256 + oh) * 256 + ow0;
        #pragma unroll
        for (int p = 0; p < 4; p++) {
            float2 e0 = upk2(ae[p]), e1 = upk2(ae[4+p]), e2 = upk2(ae[8+p]), e3 = upk2(ae[12+p]);
            float2 q0 = upk2(ao[p]), q1 = upk2(ao[4+p]), q2 = upk2(ao[8+p]), q3 = upk2(ao[12+p]);
            float* d0 = op + (size_t)(2*p) * 65536;
            float* d1 = d0 + 65536;
            *(float4*)d0       = make_float4(rl(e0.x), rl(q0.x), rl(e1.x), rl(q1.x));
            *(float4*)(d0 + 4) = make_float4(rl(e2.x), rl(q2.x), rl(e3.x), rl(q3.x));
            *(float4*)d1       = make_float4(rl(e0.y), rl(q0.y), rl(e1.y), rl(q1.y));
            *(float4*)(d1 + 4) = make_float4(rl(e2.y), rl(q2.y), rl(e3.y), rl(q3.y));
        }
    }
}

// ---------------- dec3: convT 32->3 s1 p1 + fused MSE (unchanged) --------------------
__global__ void __launch_bounds__(256) k_dec3_mse(const float* __restrict__ w,
                                                  const float* __restrict__ bias,
                                                  const float* __restrict__ x) {
    __shared__ __align__(16) ull s_wd[864];
    __shared__ ull s_bd[3];
    __shared__ float sred[32];
    for (int i = threadIdx.x; i < 864; i += 256) {
        int oc = i % 3; int t = i / 3; int kw = t % 3; t /= 3; int kh = t % 3; int ic = t / 3;
        float wv = w[ic * 27 + oc * 9 + (2 - kh) * 3 + (2 - kw)];
        s_wd[i] = pk2(wv, wv);
    }
    if (threadIdx.x < 3) { float bv = bias[threadIdx.x]; s_bd[threadIdx.x] = pk2(bv, bv); }
    __syncthreads();

    int tx = threadIdx.x;
    int chunk = tx & 31, r = tx >> 5;
    int b = blockIdx.x >> 5, rg = blockIdx.x & 31;
    int oh = rg * 8 + r;
    int ow0 = chunk * 8;

    bool ok0 = (oh > 0), ok2 = (oh < 255);
    bool eL = (chunk != 0), eR = (chunk != 31);

    ull acc[12];
    #pragma unroll
    for (int oc = 0; oc < 3; oc++) {
        ull bp = s_bd[oc];
        acc[oc*4+0] = bp; acc[oc*4+1] = bp; acc[oc*4+2] = bp; acc[oc*4+3] = bp;
    }

    #pragma unroll 1
    for (int ic = 0; ic < 32; ic++) {
        const float* rowm = g_d2 + (size_t)(b * 32 + ic) * 65536 + (oh - 1) * 256 + ow0;
        float4 m0 = ok0 ? *(const float4*)rowm       : z4();
        float4 m1 = ok0 ? *(const float4*)(rowm + 4) : z4();
        float4 c0 = *(const float4*)(rowm + 256);
        float4 c1 = *(const float4*)(rowm + 260);
        float4 b0 = ok2 ? *(const float4*)(rowm + 512) : z4();
        float4 b1 = ok2 ? *(const float4*)(rowm + 516) : z4();
        float mm1 = __shfl_up_sync(FULLMASK, m1.w, 1);   if (!eL) mm1 = 0.f;
        float cm1 = __shfl_up_sync(FULLMASK, c1.w, 1);   if (!eL) cm1 = 0.f;
        float bm1 = __shfl_up_sync(FULLMASK, b1.w, 1);   if (!eL) bm1 = 0.f;
        float m8  = __shfl_down_sync(FULLMASK, m0.x, 1); if (!eR) m8 = 0.f;
        float c8  = __shfl_down_sync(FULLMASK, c0.x, 1); if (!eR) c8 = 0.f;
        float b8  = __shfl_down_sync(FULLMASK, b0.x, 1); if (!eR) b8 = 0.f;

        const ull* wp = s_wd + ic * 27;
        #pragma unroll
        for (int kh = 0; kh < 3; kh++) {
            float4 f0 = (kh == 0) ? m0 : (kh == 1) ? c0 : b0;
            float4 f1 = (kh == 0) ? m1 : (kh == 1) ? c1 : b1;
            float vm1 = (kh == 0) ? mm1 : (kh == 1) ? cm1 : bm1;
            float v8  = (kh == 0) ? m8  : (kh == 1) ? c8  : b8;
            ull A0 = pk2(f0.x, f0.y), A1 = pk2(f0.z, f0.w), A2 = pk2(f1.x, f1.y), A3 = pk2(f1.z, f1.w);
            ull O0 = pk2(vm1, f0.x), O1 = pk2(f0.y, f0.z), O2 = pk2(f0.w, f1.x),
                O3 = pk2(f1.y, f1.z), O4 = pk2(f1.w, v8);
            const ull* wk = wp + kh * 9;
            #pragma unroll
            for (int oc = 0; oc < 3; oc++) {
                ull w0 = wk[oc], w1 = wk[3 + oc], w2 = wk[6 + oc];
                acc[oc*4+0] = ffma2(O0, w0, ffma2(A0, w1, ffma2(O1, w2, acc[oc*4+0])));
                acc[oc*4+1] = ffma2(O1, w0, ffma2(A1, w1, ffma2(O2, w2, acc[oc*4+1])));
                acc[oc*4+2] = ffma2(O2, w0, ffma2(A2, w1, ffma2(O3, w2, acc[oc*4+2])));
                acc[oc*4+3] = ffma2(O3, w0, ffma2(A3, w1, ffma2(O4, w2, acc[oc*4+3])));
            }
        }
    }

    const float* xp = x + (size_t)b * 3 * 65536 + oh * 256 + ow0;
    float sq = 0.f;
    #pragma unroll
    for (int oc = 0; oc < 3; oc++) {
        float4 x0 = *(const float4*)(xp + (size_t)oc * 65536);
        float4 x1 = *(const float4*)(xp + (size_t)oc * 65536 + 4);
        float2 p0 = upk2(acc[oc*4+0]), p1 = upk2(acc[oc*4+1]);
        float2 p2 = upk2(acc[oc*4+2]), p3 = upk2(acc[oc*4+3]);
        float e;
        e = p0.x - x0.x; sq = fmaf(e, e, sq);
        e = p0.y - x0.y; sq = fmaf(e, e, sq);
        e = p1.x - x0.z; sq = fmaf(e, e, sq);
        e = p1.y - x0.w; sq = fmaf(e, e, sq);
        e = p2.x - x1.x; sq = fmaf(e, e, sq);
        e = p2.y - x1.y; sq = fmaf(e, e, sq);
        e = p3.x - x1.z; sq = fmaf(e, e, sq);
        e = p3.y - x1.w; sq = fmaf(e, e, sq);
    }
    float bs = block_sum(sq, sred);
    if (threadIdx.x == 0) g_pmse[blockIdx.x] = bs;
}

// ---------------- deterministic final reduction ----------------
__global__ void k_final(float* __restrict__ out) {
    __shared__ double sd[256];
    double s1 = 0.0, s2 = 0.0;
    for (int i = threadIdx.x; i < 1024; i += 256) s1 += (double)g_pvq[i];
    for (int i = threadIdx.x; i < 2048; i += 256) s2 += (double)g_pmse[i];
    sd[threadIdx.x] = s1; __syncthreads();
    for (int o = 128; o > 0; o >>= 1) {
        if ((int)threadIdx.x < o) sd[threadIdx.x] += sd[threadIdx.x + o];
        __syncthreads();
    }
    double vq = sd[0]; __syncthreads();
    sd[threadIdx.x] = s2; __syncthreads();
    for (int o = 128; o > 0; o >>= 1) {
        if ((int)threadIdx.x < o) sd[threadIdx.x] += sd[threadIdx.x + o];
        __syncthreads();
    }
    if (threadIdx.x == 0) {
        double mq = vq / 4194304.0;
        double mr = sd[0] / 12582912.0;
        out[0] = (float)(1.25 * mq);
        out[1] = (float)mr;
        out[2] = (float)mr;
    }
}

// ---------------- launch ----------------
extern "C" void kernel_launch(void* const* d_in, const int* in_sizes, int n_in,
                              void* d_out, int out_size) {
    const float* x   = (const float*)d_in[0];
    const float* ew1 = (const float*)d_in[1];
    const float* eb1 = (const float*)d_in[2];
    const float* ew2 = (const float*)d_in[3];
    const float* eb2 = (const float*)d_in[4];
    const float* ew3 = (const float*)d_in[5];
    const float* eb3 = (const float*)d_in[6];
    const float* cb  = (const float*)d_in[7];
    const float* dw1 = (const float*)d_in[8];
    const float* db1 = (const float*)d_in[9];
    const float* dw2 = (const float*)d_in[10];
    const float* db2 = (const float*)d_in[11];
    const float* dw3 = (const float*)d_in[12];
    const float* db3 = (const float*)d_in[13];
    float* out = (float*)d_out;

    const int smem_enc2 = (9216 + 32) * 8;           // 73984 B
    const int smem_dec1 = 4640 * 8 + 6528 * 4;       // 63232 B
    const int smem_dec2 = (9216 + 16) * 8;           // 73856 B
    cudaFuncSetAttribute(k_enc2, cudaFuncAttributeMaxDynamicSharedMemorySize, smem_enc2);
    cudaFuncSetAttribute(k_dec1, cudaFuncAttributeMaxDynamicSharedMemorySize, smem_dec1);
    cudaFuncSetAttribute(k_dec2, cudaFuncAttributeMaxDynamicSharedMemorySize, smem_dec2);

    k_enc1    <<<2048, 256>>>(x, ew1, eb1);
    k_enc2    <<<512, 256, smem_enc2>>>(ew2, eb2);
    k_enc3_vq <<<1024, 256>>>(ew3, eb3, cb);
    k_dec1    <<<1024, 256, smem_dec1>>>(dw1, db1);
    k_dec2    <<<2048, 256, smem_dec2>>>(dw2, db2);
    k_dec3_mse<<<2048, 256>>>(dw3, db3, x);
    k_final   <<<1, 256>>>(out);
}

// round 17
// speedup vs baseline: 1.8535x; 1.0266x over previous
#include <cuda_runtime.h>

typedef unsigned long long ull;

// ---------------- scratch (device globals; no allocation allowed) ----------------
static __device__ __align__(16) float g_a1[64*32*128*128];          // enc1 out
static __device__ __align__(16) float g_a2[64*64*64*64];            // enc2 out
static __device__ __align__(16) float g_q [64*16*64*64];            // quantized (decoder input)
static __device__ __align__(16) float g_d1[64*64*128*128];          // dec1 out
static __device__ __align__(16) float g_d2[64*32*256*256];          // dec2 out
static __device__ float g_pvq [1024];                               // per-block VQ sq-sum
static __device__ float g_pmse[1024];                               // per-block recon sq-sum

#define FULLMASK 0xffffffffu

// ---------------- f32x2 helpers ----------------
__device__ __forceinline__ ull pk2(float lo, float hi) {
    ull r;
    asm("mov.b64 %0, {%1, %2};" : "=l"(r)
        : "r"(__float_as_uint(lo)), "r"(__float_as_uint(hi)));
    return r;
}
__device__ __forceinline__ float2 upk2(ull p) {
    unsigned int a, b;
    asm("mov.b64 {%0, %1}, %2;" : "=r"(a), "=r"(b) : "l"(p));
    return make_float2(__uint_as_float(a), __uint_as_float(b));
}
__device__ __forceinline__ ull ffma2(ull a, ull b, ull c) {
    ull d;
    asm("fma.rn.f32x2 %0, %1, %2, %3;" : "=l"(d) : "l"(a), "l"(b), "l"(c));
    return d;
}
__device__ __forceinline__ float4 z4() { return make_float4(0.f, 0.f, 0.f, 0.f); }
__device__ __forceinline__ float rl(float v) { return fmaxf(v, 0.f); }

// ---------------- cp.async helpers ----------------
__device__ __forceinline__ void cpa16(void* smem_dst, const void* gsrc) {
    unsigned sa = (unsigned)__cvta_generic_to_shared(smem_dst);
    asm volatile("cp.async.ca.shared.global [%0], [%1], 16;" :: "r"(sa), "l"(gsrc));
}
#define CP_COMMIT() asm volatile("cp.async.commit_group;" ::: "memory")
#define CP_WAIT1()  asm volatile("cp.async.wait_group 1;" ::: "memory")
#define CP_WAIT0()  asm volatile("cp.async.wait_group 0;" ::: "memory")

// ---------------- reduction helper ----------------
__device__ __forceinline__ float block_sum(float v, float* sred) {
    int lane = threadIdx.x & 31, w = threadIdx.x >> 5;
    #pragma unroll
    for (int o = 16; o > 0; o >>= 1) v += __shfl_down_sync(FULLMASK, v, o);
    if (lane == 0) sred[w] = v;
    __syncthreads();
    if (w == 0) {
        v = (lane < (int)(blockDim.x >> 5)) ? sred[lane] : 0.f;
        #pragma unroll
        for (int o = 16; o > 0; o >>= 1) v += __shfl_down_sync(FULLMASK, v, o);
    }
    return v;  // valid in thread 0
}

#define FMA4(ACC, J, V, W4)                         \
    do {                                            \
        ACC[4*(J)+0] = fmaf(V, (W4).x, ACC[4*(J)+0]); \
        ACC[4*(J)+1] = fmaf(V, (W4).y, ACC[4*(J)+1]); \
        ACC[4*(J)+2] = fmaf(V, (W4).z, ACC[4*(J)+2]); \
        ACC[4*(J)+3] = fmaf(V, (W4).w, ACC[4*(J)+3]); \
    } while (0)

// transposed-conv tap, oc-pair packing. Even outputs: w1*v_j. Odd: w2*v_j + w0*v_{j+1}.
__device__ __forceinline__ void ptap(float4 f, float v4,
                                     const ull* w1p, const ull* w2p, const ull* w0p,
                                     ull* ae, ull* ao) {
    ull d0 = pk2(f.x, f.x), d1 = pk2(f.y, f.y), d2 = pk2(f.z, f.z), d3 = pk2(f.w, f.w);
    ull d4 = pk2(v4, v4);
    ulonglong2 A = *(const ulonglong2*)w1p, B = *(const ulonglong2*)(w1p + 2);
    ulonglong2 C = *(const ulonglong2*)w2p, D = *(const ulonglong2*)(w2p + 2);
    ulonglong2 E = *(const ulonglong2*)w0p, F = *(const ulonglong2*)(w0p + 2);
    ull W1[4] = {A.x, A.y, B.x, B.y};
    ull W2[4] = {C.x, C.y, D.x, D.y};
    ull W0[4] = {E.x, E.y, F.x, F.y};
    #pragma unroll
    for (int p = 0; p < 4; p++) {
        ae[0*4+p] = ffma2(d0, W1[p], ae[0*4+p]);
        ae[1*4+p] = ffma2(d1, W1[p], ae[1*4+p]);
        ae[2*4+p] = ffma2(d2, W1[p], ae[2*4+p]);
        ae[3*4+p] = ffma2(d3, W1[p], ae[3*4+p]);
        ao[0*4+p] = ffma2(d1, W0[p], ffma2(d0, W2[p], ao[0*4+p]));
        ao[1*4+p] = ffma2(d2, W0[p], ffma2(d1, W2[p], ao[1*4+p]));
        ao[2*4+p] = ffma2(d3, W0[p], ffma2(d2, W2[p], ao[2*4+p]));
        ao[3*4+p] = ffma2(d4, W0[p], ffma2(d3, W2[p], ao[3*4+p]));
    }
}

// ---------------- enc1: conv 3->32, k3 s2 p1, ReLU (P=2 px, oc-pair) ----------------
__global__ void __launch_bounds__(256) k_enc1(const float* __restrict__ x,
                                              const float* __restrict__ w,
                                              const float* __restrict__ bias) {
    __shared__ __align__(16) ull s_wp[432];   // [t = ic*9+kh*3+kw][16 ocp]
    __shared__ ull s_bd[16];
    for (int i = threadIdx.x; i < 432; i += 256) {
        int ocp = i & 15, t = i >> 4;
        s_wp[i] = pk2(w[(2 * ocp) * 27 + t], w[(2 * ocp + 1) * 27 + t]);
    }
    if (threadIdx.x < 16) s_bd[threadIdx.x] = pk2(bias[2*threadIdx.x], bias[2*threadIdx.x+1]);
    __syncthreads();

    int tid = blockIdx.x * 256 + threadIdx.x;      // 64*128*64 threads
    int j = tid & 63, oh = (tid >> 6) & 127, b = tid >> 13;
    int lane = threadIdx.x & 31;

    ull a0[16], a1[16];
    #pragma unroll
    for (int p = 0; p < 16; p++) { a0[p] = s_bd[p]; a1[p] = s_bd[p]; }

    #pragma unroll
    for (int ic = 0; ic < 3; ic++) {
        const float* xp = x + (size_t)(b * 3 + ic) * 65536;
        #pragma unroll
        for (int kh = 0; kh < 3; kh++) {
            int ih = 2 * oh + kh - 1;
            bool okh = (unsigned)ih < 256u;
            const float* row = xp + ih * 256 + 4 * j;
            float4 f = okh ? *(const float4*)row : z4();
            float vL = __shfl_up_sync(FULLMASK, f.w, 1);
            if (lane == 0) vL = (okh && j > 0) ? row[-1] : 0.f;
            ull dL = pk2(vL, vL), dx = pk2(f.x, f.x), dy = pk2(f.y, f.y);
            ull dz = pk2(f.z, f.z), dw_ = pk2(f.w, f.w);
            const ull* wb = s_wp + (ic * 9 + kh * 3) * 16;
            #pragma unroll
            for (int kw = 0; kw < 3; kw++) {
                ull da = (kw == 0) ? dL : (kw == 1) ? dx : dy;
                ull db = (kw == 0) ? dy : (kw == 1) ? dz : dw_;
                const ull* wk = wb + kw * 16;
                #pragma unroll
                for (int p = 0; p < 16; p += 2) {
                    ulonglong2 wp2 = *(const ulonglong2*)(wk + p);
                    a0[p]     = ffma2(da, wp2.x, a0[p]);
                    a0[p + 1] = ffma2(da, wp2.y, a0[p + 1]);
                    a1[p]     = ffma2(db, wp2.x, a1[p]);
                    a1[p + 1] = ffma2(db, wp2.y, a1[p + 1]);
                }
            }
        }
    }
    float* op = g_a1 + (size_t)b * 32 * 16384 + oh * 128 + 2 * j;
    #pragma unroll
    for (int p = 0; p < 16; p++) {
        float2 v0 = upk2(a0[p]);
        float2 v1 = upk2(a1[p]);
        float2 e;
        e.x = rl(v0.x); e.y = rl(v1.x); *(float2*)(op + (size_t)(2*p)   * 16384) = e;
        e.x = rl(v0.y); e.y = rl(v1.y); *(float2*)(op + (size_t)(2*p+1) * 16384) = e;
    }
}

// ---------------- enc2: conv 32->64, k3 s2 p1, ReLU (P=8, oc-pair, RR=2) ------------
__global__ void __launch_bounds__(256, 2) k_enc2(const float* __restrict__ w,
                                                 const float* __restrict__ bias) {
    extern __shared__ __align__(16) ull smu[];
    ull* s_w = smu;               // 9216: [kh][ic][kw][32 ocp]
    ull* s_bd = smu + 9216;       // 32
    for (int i = threadIdx.x; i < 9216; i += 256) {
        int ocp = i & 31; int q = i >> 5; int kw = q % 3; int t2 = q / 3;
        int ic = t2 & 31; int kh = t2 >> 5;
        s_w[i] = pk2(w[(2*ocp)     * 288 + ic * 9 + kh * 3 + kw],
                     w[(2*ocp + 1) * 288 + ic * 9 + kh * 3 + kw]);
    }
    if (threadIdx.x < 32) s_bd[threadIdx.x] = pk2(bias[2*threadIdx.x], bias[2*threadIdx.x+1]);
    __syncthreads();

    int tx = threadIdx.x;
    int chunk = tx & 7, ocg = (tx >> 3) & 7, r = tx >> 6;
    int b = blockIdx.x >> 3, rg = blockIdx.x & 7;
    int ocp0 = ocg * 4;
    int ow0 = chunk * 8;

    #pragma unroll 1
    for (int rr = 0; rr < 2; rr++) {
        int oh = rg * 8 + rr * 4 + r;

        ull acc[32];
        #pragma unroll
        for (int p = 0; p < 4; p++) {
            ull bp = s_bd[ocp0 + p];
            #pragma unroll
            for (int owl = 0; owl < 8; owl++) acc[owl*4+p] = bp;
        }

        #pragma unroll 1
        for (int ic = 0; ic < 32; ic++) {
            const float* plane = g_a1 + (size_t)(b * 32 + ic) * 16384;
            #pragma unroll
            for (int kh = 0; kh < 3; kh++) {
                int ih = 2 * oh + kh - 1;
                if ((unsigned)ih >= 128u) continue;
                const float* row = plane + ih * 128 + chunk * 16;
                float4 g0 = *(const float4*)row;
                float4 g1 = *(const float4*)(row + 4);
                float4 g2 = *(const float4*)(row + 8);
                float4 g3 = *(const float4*)(row + 12);
                float vm1 = __shfl_up_sync(FULLMASK, g3.w, 1);
                if (chunk == 0) vm1 = 0.f;
                const ull* wb = s_w + ((kh * 32 + ic) * 3) * 32 + ocp0;
                ulonglong2 wa0 = *(const ulonglong2*)(wb),      wb0 = *(const ulonglong2*)(wb + 2);
                ulonglong2 wa1 = *(const ulonglong2*)(wb + 32), wb1 = *(const ulonglong2*)(wb + 34);
                ulonglong2 wa2 = *(const ulonglong2*)(wb + 64), wb2 = *(const ulonglong2*)(wb + 66);
                ull W0[4] = {wa0.x, wa0.y, wb0.x, wb0.y};
                ull W1[4] = {wa1.x, wa1.y, wb1.x, wb1.y};
                ull W2[4] = {wa2.x, wa2.y, wb2.x, wb2.y};
                float s[17] = {vm1, g0.x, g0.y, g0.z, g0.w, g1.x, g1.y, g1.z, g1.w,
                               g2.x, g2.y, g2.z, g2.w, g3.x, g3.y, g3.z, g3.w};
                #pragma unroll
                for (int owl = 0; owl < 8; owl++) {
                    ull dA = pk2(s[2*owl],     s[2*owl]);
                    ull dB = pk2(s[2*owl + 1], s[2*owl + 1]);
                    ull dC = pk2(s[2*owl + 2], s[2*owl + 2]);
                    #pragma unroll
                    for (int p = 0; p < 4; p++)
                        acc[owl*4+p] = ffma2(dA, W0[p], ffma2(dB, W1[p], ffma2(dC, W2[p], acc[owl*4+p])));
                }
            }
        }

        float* op = g_a2 + ((size_t)(b * 64 + ocg * 8) * 64 + oh) * 64 + ow0;
        #pragma unroll
        for (int p = 0; p < 4; p++) {
            float2 q0 = upk2(acc[0*4+p]), q1 = upk2(acc[1*4+p]), q2 = upk2(acc[2*4+p]), q3 = upk2(acc[3*4+p]);
            float2 q4 = upk2(acc[4*4+p]), q5 = upk2(acc[5*4+p]), q6 = upk2(acc[6*4+p]), q7 = upk2(acc[7*4+p]);
            float* d0 = op + (size_t)(2*p) * 4096;
            float* d1 = d0 + 4096;
            *(float4*)d0       = make_float4(rl(q0.x), rl(q1.x), rl(q2.x), rl(q3.x));
            *(float4*)(d0 + 4) = make_float4(rl(q4.x), rl(q5.x), rl(q6.x), rl(q7.x));
            *(float4*)d1       = make_float4(rl(q0.y), rl(q1.y), rl(q2.y), rl(q3.y));
            *(float4*)(d1 + 4) = make_float4(rl(q4.y), rl(q5.y), rl(q6.y), rl(q7.y));
        }
    }
}

// ---------------- enc3 (1x1, 64->16) + VQ + q-loss (R11 scalar scan) -----------------
__global__ void __launch_bounds__(256) k_enc3_vq(const float* __restrict__ w3,
                                                 const float* __restrict__ b3,
                                                 const float* __restrict__ cb) {
    __shared__ __align__(16) float s_w[64 * 16];
    __shared__ float s_b[16];
    __shared__ __align__(16) float s_cb[512 * 16];
    __shared__ float s_cn[512];
    __shared__ float sred[32];

    for (int i = threadIdx.x; i < 1024; i += 256) {
        int d = i & 15, ic = i >> 4;
        s_w[i] = w3[d * 64 + ic];
    }
    if (threadIdx.x < 16) s_b[threadIdx.x] = b3[threadIdx.x];
    for (int i = threadIdx.x; i < 8192; i += 256) s_cb[i] = cb[i];
    __syncthreads();
    for (int j = threadIdx.x; j < 512; j += 256) {
        float s = 0.f;
        #pragma unroll
        for (int d = 0; d < 16; d++) { float c = s_cb[j * 16 + d]; s = fmaf(c, c, s); }
        s_cn[j] = s;
    }
    __syncthreads();

    int tid = blockIdx.x * 256 + threadIdx.x;
    int p = tid & 4095, b = tid >> 12;

    float z[16];
    #pragma unroll
    for (int d = 0; d < 16; d++) z[d] = s_b[d];
    const float* ap = g_a2 + (size_t)b * 64 * 4096 + p;
    #pragma unroll 8
    for (int ic = 0; ic < 64; ic++) {
        float v = ap[ic * 4096];
        const float4* wp = (const float4*)&s_w[ic * 16];
        #pragma unroll
        for (int j = 0; j < 4; j++) { float4 w4 = wp[j]; FMA4(z, j, v, w4); }
    }

    int best = 0; float bd = 3.4e38f;
    for (int j = 0; j < 512; j++) {
        const float4* cp = (const float4*)&s_cb[j * 16];
        float dot = 0.f;
        #pragma unroll
        for (int q4 = 0; q4 < 4; q4++) {
            float4 c4 = cp[q4];
            dot = fmaf(z[4*q4+0], c4.x, dot);
            dot = fmaf(z[4*q4+1], c4.y, dot);
            dot = fmaf(z[4*q4+2], c4.z, dot);
            dot = fmaf(z[4*q4+3], c4.w, dot);
        }
        float dist = s_cn[j] - 2.f * dot;
        if (dist < bd) { bd = dist; best = j; }
    }

    float sq = 0.f;
    float* qp = g_q + (size_t)b * 16 * 4096 + p;
    #pragma unroll
    for (int d = 0; d < 16; d++) {
        float qv = s_cb[best * 16 + d];
        float df = qv - z[d];
        sq = fmaf(df, df, sq);
        qp[d * 4096] = qv;
    }
    float bs = block_sum(sq, sred);
    if (threadIdx.x == 0) g_pvq[blockIdx.x] = bs;
}

// ---------------- dec1: convT 16->64 (cp.async double-buffered, RR=4, grid 1024) -----
__device__ __forceinline__ void dec1_stage(float* sbuf, int b, int Rbase, int nr, int tid) {
    int nf4 = 16 * nr * 16;
    for (int i = tid; i < nf4; i += 256) {
        int c4 = i & 15; int q = i >> 4; int row = q % nr; int ic = q / nr;
        int gr = Rbase + row;
        float* dst = sbuf + (ic * nr + row) * 68 + c4 * 4;
        if (gr < 64) cpa16(dst, g_q + ((size_t)b * 16 + ic) * 4096 + gr * 64 + c4 * 4);
        else *(float4*)dst = z4();
    }
}

__global__ void __launch_bounds__(256, 2) k_dec1(const float* __restrict__ w,
                                                 const float* __restrict__ bias) {
    extern __shared__ __align__(16) ull smu[];
    ull* s_w1 = smu;              // [kh][ic][32 ocp]
    ull* s_w2 = smu + 1536;
    ull* s_w0 = smu + 3072;
    ull* s_bd = smu + 4608;       // 32
    float* s_in = (float*)(smu + 4640);   // 2 x 3264 floats
    for (int i = threadIdx.x; i < 1536; i += 256) {
        int ocp = i & 31, ic = (i >> 5) & 15, kh = i >> 9;
        const float* wa = w + ((ic * 64 + 2 * ocp) * 3 + kh) * 3;
        const float* wb = w + ((ic * 64 + 2 * ocp + 1) * 3 + kh) * 3;
        s_w1[i] = pk2(wa[1], wb[1]);
        s_w2[i] = pk2(wa[2], wb[2]);
        s_w0[i] = pk2(wa[0], wb[0]);
    }
    if (threadIdx.x < 32) s_bd[threadIdx.x] = pk2(bias[2*threadIdx.x], bias[2*threadIdx.x+1]);
    for (int i = threadIdx.x; i < 6528; i += 256) s_in[i] = 0.f;
    __syncthreads();

    int tx = threadIdx.x;
    int chunk = tx & 15, ocg = (tx >> 4) & 7, r = tx >> 7;
    int bi = blockIdx.x;
    int b = bi >> 4, rem = bi & 15, ph = rem >> 3, rg = rem & 7;
    int ocp0 = ocg * 4;
    int ow0 = chunk * 8;
    int nr = ph ? 3 : 2;

    dec1_stage(s_in, b, rg * 8, nr, tx); CP_COMMIT();

    #pragma unroll 1
    for (int rr = 0; rr < 4; rr++) {
        int buf = rr & 1;
        if (rr < 3) {
            dec1_stage(s_in + (buf ^ 1) * 3264, b, rg * 8 + (rr + 1) * 2, nr, tx);
            CP_COMMIT(); CP_WAIT1();
        } else CP_WAIT0();
        __syncthreads();

        int R = rg * 8 + rr * 2 + r;
        int oh = 2 * R + ph;
        const float* bufp = s_in + buf * 3264;

        ull ae[16], ao[16];
        #pragma unroll
        for (int p = 0; p < 4; p++) {
            ull bp = s_bd[ocp0 + p];
            ae[p] = bp; ae[4+p] = bp; ae[8+p] = bp; ae[12+p] = bp;
            ao[p] = bp; ao[4+p] = bp; ao[8+p] = bp; ao[12+p] = bp;
        }

        if (ph == 0) {
            #pragma unroll 4
            for (int ic = 0; ic < 16; ic++) {
                const float* rp = bufp + (ic * 2 + r) * 68 + chunk * 4;
                float4 f = *(const float4*)rp; float v4 = rp[4];
                int t0 = (16 + ic) * 32 + ocp0;
                ptap(f, v4, s_w1 + t0, s_w2 + t0, s_w0 + t0, ae, ao);
            }
        } else {
            #pragma unroll 2
            for (int ic = 0; ic < 16; ic++) {
                const float* rpA = bufp + (ic * 3 + r) * 68 + chunk * 4;
                const float* rpB = rpA + 68;
                float4 fa = *(const float4*)rpA; float va = rpA[4];
                float4 fb = *(const float4*)rpB; float vb = rpB[4];
                int ta = (32 + ic) * 32 + ocp0;   // kh=2 @ R
                int tb = ic * 32 + ocp0;          // kh=0 @ R+1
                ptap(fa, va, s_w1 + ta, s_w2 + ta, s_w0 + ta, ae, ao);
                ptap(fb, vb, s_w1 + tb, s_w2 + tb, s_w0 + tb, ae, ao);
            }
        }

        float* op = g_d1 + ((size_t)(b * 64 + ocg * 8) * 128 + oh) * 128 + ow0;
        #pragma unroll
        for (int p = 0; p < 4; p++) {
            float2 e0 = upk2(ae[p]), e1 = upk2(ae[4+p]), e2 = upk2(ae[8+p]), e3 = upk2(ae[12+p]);
            float2 q0 = upk2(ao[p]), q1 = upk2(ao[4+p]), q2 = upk2(ao[8+p]), q3 = upk2(ao[12+p]);
            float* d0 = op + (size_t)(2*p) * 16384;
            float* d1 = d0 + 16384;
            *(float4*)d0       = make_float4(rl(e0.x), rl(q0.x), rl(e1.x), rl(q1.x));
            *(float4*)(d0 + 4) = make_float4(rl(e2.x), rl(q2.x), rl(e3.x), rl(q3.x));
            *(float4*)d1       = make_float4(rl(e0.y), rl(q0.y), rl(e1.y), rl(q1.y));
            *(float4*)(d1 + 4) = make_float4(rl(e2.y), rl(q2.y), rl(e3.y), rl(q3.y));
        }
        __syncthreads();
    }
}

// ---------------- dec2: convT 64->32 (oc-pair, direct LDG, balanced phases) ----------
// grid: 64b * 48 units = 3072. units 0..15: ph=0, RR=4. units 16..47: ph=1, RR=2.
// All blocks perform exactly 4 tap-rows of work (uniform duration).
__global__ void __launch_bounds__(256, 2) k_dec2(const float* __restrict__ w,
                                                 const float* __restrict__ bias) {
    extern __shared__ __align__(16) ull smu[];
    ull* s_w1 = smu;              // [kh][ic][16 ocp] 3072 each
    ull* s_w2 = smu + 3072;
    ull* s_w0 = smu + 6144;
    ull* s_bd = smu + 9216;       // 16
    for (int i = threadIdx.x; i < 3072; i += 256) {
        int ocp = i & 15, ic = (i >> 4) & 63, kh = i >> 10;
        const float* wa = w + ((ic * 32 + 2 * ocp) * 3 + kh) * 3;       // dec_w2 [64][32][3][3]
        const float* wb = w + ((ic * 32 + 2 * ocp + 1) * 3 + kh) * 3;
        s_w1[i] = pk2(wa[1], wb[1]);
        s_w2[i] = pk2(wa[2], wb[2]);
        s_w0[i] = pk2(wa[0], wb[0]);
    }
    if (threadIdx.x < 16) s_bd[threadIdx.x] = pk2(bias[2*threadIdx.x], bias[2*threadIdx.x+1]);
    __syncthreads();

    int tx = threadIdx.x;
    int chunk = tx & 31, ocg = (tx >> 5) & 3, r = tx >> 7;
    int bi = blockIdx.x;
    int b = bi / 48, u = bi - b * 48;
    int ph, Rbase, RRn;
    if (u < 16) { ph = 0; Rbase = u * 8; RRn = 4; }
    else        { ph = 1; Rbase = (u - 16) * 4; RRn = 2; }
    int ocp0 = ocg * 4;
    int ow0 = chunk * 8;
    const float* base = g_d1 + (size_t)b * 64 * 16384 + chunk * 4;
    bool edge = (chunk < 31);

    #pragma unroll 1
    for (int rr = 0; rr < RRn; rr++) {
        int R = Rbase + rr * 2 + r;
        int oh = 2 * R + ph;

        ull ae[16], ao[16];
        #pragma unroll
        for (int p = 0; p < 4; p++) {
            ull bp = s_bd[ocp0 + p];
            ae[p] = bp; ae[4+p] = bp; ae[8+p] = bp; ae[12+p] = bp;
            ao[p] = bp; ao[4+p] = bp; ao[8+p] = bp; ao[12+p] = bp;
        }

        if (ph == 0) {             // single tap kh=1 @ row R; ic-unroll 4
            const float* p0 = base + R * 128;
            #pragma unroll 1
            for (int ic = 0; ic < 64; ic += 4) {
                float4 f0 = *(const float4*)(p0 + (size_t)(ic + 0) * 16384);
                float4 f1 = *(const float4*)(p0 + (size_t)(ic + 1) * 16384);
                float4 f2 = *(const float4*)(p0 + (size_t)(ic + 2) * 16384);
                float4 f3 = *(const float4*)(p0 + (size_t)(ic + 3) * 16384);
                float v0 = __shfl_down_sync(FULLMASK, f0.x, 1); if (!edge) v0 = 0.f;
                float v1 = __shfl_down_sync(FULLMASK, f1.x, 1); if (!edge) v1 = 0.f;
                float v2 = __shfl_down_sync(FULLMASK, f2.x, 1); if (!edge) v2 = 0.f;
                float v3 = __shfl_down_sync(FULLMASK, f3.x, 1); if (!edge) v3 = 0.f;
                int t0 = (64 + ic) * 16 + ocp0;
                ptap(f0, v0, s_w1 + t0,      s_w2 + t0,      s_w0 + t0,      ae, ao);
                ptap(f1, v1, s_w1 + t0 + 16, s_w2 + t0 + 16, s_w0 + t0 + 16, ae, ao);
                ptap(f2, v2, s_w1 + t0 + 32, s_w2 + t0 + 32, s_w0 + t0 + 32, ae, ao);
                ptap(f3, v3, s_w1 + t0 + 48, s_w2 + t0 + 48, s_w0 + t0 + 48, ae, ao);
            }
        } else {                   // taps kh=2 @ R, kh=0 @ R+1; ic-unroll 2
            bool ok = (R + 1 < 128);
            const float* pa = base + R * 128;
            const float* pb = base + (R + 1) * 128;
            #pragma unroll 1
            for (int ic = 0; ic < 64; ic += 2) {
                float4 fa0 = *(const float4*)(pa + (size_t)ic * 16384);
                float4 fa1 = *(const float4*)(pa + (size_t)(ic + 1) * 16384);
                float4 fb0 = ok ? *(const float4*)(pb + (size_t)ic * 16384) : z4();
                float4 fb1 = ok ? *(const float4*)(pb + (size_t)(ic + 1) * 16384) : z4();
                float va0 = __shfl_down_sync(FULLMASK, fa0.x, 1); if (!edge) va0 = 0.f;
                float va1 = __shfl_down_sync(FULLMASK, fa1.x, 1); if (!edge) va1 = 0.f;
                float vb0 = __shfl_down_sync(FULLMASK, fb0.x, 1); if (!edge) vb0 = 0.f;
                float vb1 = __shfl_down_sync(FULLMASK, fb1.x, 1); if (!edge) vb1 = 0.f;
                int ta = (128 + ic) * 16 + ocp0;   // kh=2
                int tb = ic * 16 + ocp0;           // kh=0
                ptap(fa0, va0, s_w1 + ta,      s_w2 + ta,      s_w0 + ta,      ae, ao);
                ptap(fb0, vb0, s_w1 + tb,      s_w2 + tb,      s_w0 + tb,      ae, ao);
                ptap(fa1, va1, s_w1 + ta + 16, s_w2 + ta + 16, s_w0 + ta + 16, ae, ao);
                ptap(fb1, vb1, s_w1 + tb + 16, s_w2 + tb + 16, s_w0 + tb + 16, ae, ao);
            }
        }

        float* op = g_d2 + ((size_t)(b * 32 + ocg * 8) * 256 + oh) * 256 + ow0;
        #pragma unroll
        for (int p = 0; p < 4; p++) {
            float2 e0 = upk2(ae[p]), e1 = upk2(ae[4+p]), e2 = upk2(ae[8+p]), e3 = upk2(ae[12+p]);
            float2 q0 = upk2(ao[p]), q1 = upk2(ao[4+p]), q2 = upk2(ao[8+p]), q3 = upk2(ao[12+p]);
            float* d0 = op + (size_t)(2*p) * 65536;
            float* d1 = d0 + 65536;
            *(float4*)d0       = make_float4(rl(e0.x), rl(q0.x), rl(e1.x), rl(q1.x));
            *(float4*)(d0 + 4) = make_float4(rl(e2.x), rl(q2.x), rl(e3.x), rl(q3.x));
            *(float4*)d1       = make_float4(rl(e0.y), rl(q0.y), rl(e1.y), rl(q1.y));
            *(float4*)(d1 + 4) = make_float4(rl(e2.y), rl(q2.y), rl(e3.y), rl(q3.y));
        }
    }
}

// ---------------- dec3: convT 32->3 s1 p1 + fused MSE (row-pair, 4-row loads) --------
// block: chunk(32) x r(8) = 256. grid: 64b * 16rg = 1024. Each thread: oh0=rg*16+2r, oh1=oh0+1.
__global__ void __launch_bounds__(256) k_dec3_mse(const float* __restrict__ w,
                                                  const float* __restrict__ bias,
                                                  const float* __restrict__ x) {
    __shared__ __align__(16) ull s_wd[864];   // [ic][kh][kw][oc] dup pairs (flipped kernel)
    __shared__ ull s_bd[3];
    __shared__ float sred[32];
    for (int i = threadIdx.x; i < 864; i += 256) {
        int oc = i % 3; int t = i / 3; int kw = t % 3; t /= 3; int kh = t % 3; int ic = t / 3;
        float wv = w[ic * 27 + oc * 9 + (2 - kh) * 3 + (2 - kw)];
        s_wd[i] = pk2(wv, wv);
    }
    if (threadIdx.x < 3) { float bv = bias[threadIdx.x]; s_bd[threadIdx.x] = pk2(bv, bv); }
    __syncthreads();

    int tx = threadIdx.x;
    int chunk = tx & 31, r = tx >> 5;
    int b = blockIdx.x >> 4, rg = blockIdx.x & 15;
    int oh0 = rg * 16 + 2 * r;               // even; oh1 = oh0+1
    int ow0 = chunk * 8;

    bool ok0 = (oh0 > 0);                    // row oh0-1 valid
    bool ok3 = (oh0 + 2 < 256);              // row oh0+2 valid
    bool eL = (chunk != 0), eR = (chunk != 31);

    ull acc[24];                             // [out][oc][4 pairs]
    #pragma unroll
    for (int oc = 0; oc < 3; oc++) {
        ull bp = s_bd[oc];
        #pragma unroll
        for (int q = 0; q < 4; q++) { acc[oc*4+q] = bp; acc[12 + oc*4+q] = bp; }
    }

    #pragma unroll 1
    for (int ic = 0; ic < 32; ic++) {
        const float* rowm = g_d2 + (size_t)(b * 32 + ic) * 65536 + (oh0 - 1) * 256 + ow0;
        // 4 input rows (oh0-1 .. oh0+2), batched loads (MLP=8)
        float4 R0a = ok0 ? *(const float4*)rowm         : z4();
        float4 R0b = ok0 ? *(const float4*)(rowm + 4)   : z4();
        float4 R1a = *(const float4*)(rowm + 256);
        float4 R1b = *(const float4*)(rowm + 260);
        float4 R2a = *(const float4*)(rowm + 512);
        float4 R2b = *(const float4*)(rowm + 516);
        float4 R3a = ok3 ? *(const float4*)(rowm + 768) : z4();
        float4 R3b = ok3 ? *(const float4*)(rowm + 772) : z4();
        float L0 = __shfl_up_sync(FULLMASK, R0b.w, 1);   if (!eL) L0 = 0.f;
        float L1 = __shfl_up_sync(FULLMASK, R1b.w, 1);   if (!eL) L1 = 0.f;
        float L2 = __shfl_up_sync(FULLMASK, R2b.w, 1);   if (!eL) L2 = 0.f;
        float L3 = __shfl_up_sync(FULLMASK, R3b.w, 1);   if (!eL) L3 = 0.f;
        float Rr0 = __shfl_down_sync(FULLMASK, R0a.x, 1); if (!eR) Rr0 = 0.f;
        float Rr1 = __shfl_down_sync(FULLMASK, R1a.x, 1); if (!eR) Rr1 = 0.f;
        float Rr2 = __shfl_down_sync(FULLMASK, R2a.x, 1); if (!eR) Rr2 = 0.f;
        float Rr3 = __shfl_down_sync(FULLMASK, R3a.x, 1); if (!eR) Rr3 = 0.f;

        const ull* wp = s_wd + ic * 27;      // [kh][kw][oc]
        #pragma unroll
        for (int out = 0; out < 2; out++) {
            ull* ac = acc + out * 12;
            #pragma unroll
            for (int kh = 0; kh < 3; kh++) {
                int row = out + kh;          // 0..3
                float4 f0 = (row == 0) ? R0a : (row == 1) ? R1a : (row == 2) ? R2a : R3a;
                float4 f1 = (row == 0) ? R0b : (row == 1) ? R1b : (row == 2) ? R2b : R3b;
                float vm1 = (row == 0) ? L0 : (row == 1) ? L1 : (row == 2) ? L2 : L3;
                float v8  = (row == 0) ? Rr0 : (row == 1) ? Rr1 : (row == 2) ? Rr2 : Rr3;
                ull A0 = pk2(f0.x, f0.y), A1 = pk2(f0.z, f0.w), A2 = pk2(f1.x, f1.y), A3 = pk2(f1.z, f1.w);
                ull O0 = pk2(vm1, f0.x), O1 = pk2(f0.y, f0.z), O2 = pk2(f0.w, f1.x),
                    O3 = pk2(f1.y, f1.z), O4 = pk2(f1.w, v8);
                const ull* wk = wp + kh * 9;
                #pragma unroll
                for (int oc = 0; oc < 3; oc++) {
                    ull w0 = wk[oc], w1 = wk[3 + oc], w2 = wk[6 + oc];
                    ac[oc*4+0] = ffma2(O0, w0, ffma2(A0, w1, ffma2(O1, w2, ac[oc*4+0])));
                    ac[oc*4+1] = ffma2(O1, w0, ffma2(A1, w1, ffma2(O2, w2, ac[oc*4+1])));
                    ac[oc*4+2] = ffma2(O2, w0, ffma2(A2, w1, ffma2(O3, w2, ac[oc*4+2])));
                    ac[oc*4+3] = ffma2(O3, w0, ffma2(A3, w1, ffma2(O4, w2, ac[oc*4+3])));
                }
            }
        }
    }

    float sq = 0.f;
    #pragma unroll
    for (int out = 0; out < 2; out++) {
        const float* xp = x + (size_t)b * 3 * 65536 + (oh0 + out) * 256 + ow0;
        const ull* ac = acc + out * 12;
        #pragma unroll
        for (int oc = 0; oc < 3; oc++) {
            float4 x0 = *(const float4*)(xp + (size_t)oc * 65536);
            float4 x1 = *(const float4*)(xp + (size_t)oc * 65536 + 4);
            float2 p0 = upk2(ac[oc*4+0]), p1 = upk2(ac[oc*4+1]);
            float2 p2 = upk2(ac[oc*4+2]), p3 = upk2(ac[oc*4+3]);
            float e;
            e = p0.x - x0.x; sq = fmaf(e, e, sq);
            e = p0.y - x0.y; sq = fmaf(e, e, sq);
            e = p1.x - x0.z; sq = fmaf(e, e, sq);
            e = p1.y - x0.w; sq = fmaf(e, e, sq);
            e = p2.x - x1.x; sq = fmaf(e, e, sq);
            e = p2.y - x1.y; sq = fmaf(e, e, sq);
            e = p3.x - x1.z; sq = fmaf(e, e, sq);
            e = p3.y - x1.w; sq = fmaf(e, e, sq);
        }
    }
    float bs = block_sum(sq, sred);
    if (threadIdx.x == 0) g_pmse[blockIdx.x] = bs;
}

// ---------------- deterministic final reduction ----------------
__global__ void k_final(float* __restrict__ out) {
    __shared__ double sd[256];
    double s1 = 0.0, s2 = 0.0;
    for (int i = threadIdx.x; i < 1024; i += 256) s1 += (double)g_pvq[i];
    for (int i = threadIdx.x; i < 1024; i += 256) s2 += (double)g_pmse[i];
    sd[threadIdx.x] = s1; __syncthreads();
    for (int o = 128; o > 0; o >>= 1) {
        if ((int)threadIdx.x < o) sd[threadIdx.x] += sd[threadIdx.x + o];
        __syncthreads();
    }
    double vq = sd[0]; __syncthreads();
    sd[threadIdx.x] = s2; __syncthreads();
    for (int o = 128; o > 0; o >>= 1) {
        if ((int)threadIdx.x < o) sd[threadIdx.x] += sd[threadIdx.x + o];
        __syncthreads();
    }
    if (threadIdx.x == 0) {
        double mq = vq / 4194304.0;                 // 64*64*64*16
        double mr = sd[0] / 12582912.0;             // 64*3*256*256
        out[0] = (float)(1.25 * mq);
        out[1] = (float)mr;
        out[2] = (float)mr;
    }
}

// ---------------- launch ----------------
extern "C" void kernel_launch(void* const* d_in, const int* in_sizes, int n_in,
                              void* d_out, int out_size) {
    const float* x   = (const float*)d_in[0];
    const float* ew1 = (const float*)d_in[1];
    const float* eb1 = (const float*)d_in[2];
    const float* ew2 = (const float*)d_in[3];
    const float* eb2 = (const float*)d_in[4];
    const float* ew3 = (const float*)d_in[5];
    const float* eb3 = (const float*)d_in[6];
    const float* cb  = (const float*)d_in[7];
    const float* dw1 = (const float*)d_in[8];
    const float* db1 = (const float*)d_in[9];
    const float* dw2 = (const float*)d_in[10];
    const float* db2 = (const float*)d_in[11];
    const float* dw3 = (const float*)d_in[12];
    const float* db3 = (const float*)d_in[13];
    float* out = (float*)d_out;

    const int smem_enc2 = (9216 + 32) * 8;           // 73984 B
    const int smem_dec1 = 4640 * 8 + 6528 * 4;       // 63232 B
    const int smem_dec2 = (9216 + 16) * 8;           // 73856 B
    cudaFuncSetAttribute(k_enc2, cudaFuncAttributeMaxDynamicSharedMemorySize, smem_enc2);
    cudaFuncSetAttribute(k_dec1, cudaFuncAttributeMaxDynamicSharedMemorySize, smem_dec1);
    cudaFuncSetAttribute(k_dec2, cudaFuncAttributeMaxDynamicSharedMemorySize, smem_dec2);

    k_enc1    <<<2048, 256>>>(x, ew1, eb1);
    k_enc2    <<<512, 256, smem_enc2>>>(ew2, eb2);
    k_enc3_vq <<<1024, 256>>>(ew3, eb3, cb);
    k_dec1    <<<1024, 256, smem_dec1>>>(dw1, db1);
    k_dec2    <<<3072, 256, smem_dec2>>>(dw2, db2);
    k_dec3_mse<<<1024, 256>>>(dw3, db3, x);
    k_final   <<<1, 256>>>(out);
}